// round 11
// baseline (speedup 1.0000x reference)
#include <cuda_runtime.h>
#include <cuda_bf16.h>
#include <math.h>
#include <stdint.h>

// ---------------------------------------------------------------------------
// HybridTTLayer via mma.sync bf16 tensor cores (plain sm_100 target).
// fp32 emulated as bf16 hi+lo split, 3-product MMA.
// R11: per block, dense+gate GEMMs fused into ONE kernel using the identity
//   LN(t)@W = iv*(t@(gamma.*W)) - mu*iv*(gamma^T W) + beta^T W
// so both GEMMs share A=t (or x). Epilogue does LN-correction + bias + gelu +
// sigmoid gate + combine. TT GEMM keeps the proven R10 path.
// ---------------------------------------------------------------------------

#define NTOK   4096
#define DIN    1024
#define DOUT   4096

#define OP_NONE 0

// GEMM tiling (shared by TT kernel and fused kernel)
#define BM 128
#define BN 128
#define BK 32
#define STAGES 3
// TT kernel stage layout (4 matrices)
#define OFF_AH 0
#define OFF_AL 8192
#define OFF_BH 16384
#define OFF_BL 24576
#define STAGE_BYTES 32768
#define GEMM_SMEM (STAGES * STAGE_BYTES)     // 98304 -> 2 CTAs/SM
// fused kernel stage layout (6 matrices)
#define F_AH 0
#define F_AL 8192
#define F_DH 16384
#define F_DL 24576
#define F_GH 32768
#define F_GL 40960
#define F_STAGE 49152
#define F_SMEM (STAGES * F_STAGE)            // 147456 -> 1 CTA/SM

// swizzled byte offset of 16B chunk c (0..3) in row r (64B rows)
__device__ __forceinline__ uint32_t swz(int r, int c) {
    return (uint32_t)(r * 64 + ((c ^ ((r >> 1) & 3)) << 4));
}

// ------------------------- scratch (static device memory) ------------------
__device__ float g_t  [NTOK * DOUT];
__device__ float g_a01[8 * 8 * 8 * 16 * 16];
__device__ float g_mu1[NTOK], g_iv1[NTOK];
__device__ float g_mu2[NTOK], g_iv2[NTOK];
__device__ float g_vGW1[DIN],  g_vBW1[DIN];
__device__ float g_vGW2[DOUT], g_vBW2[DOUT];
__device__ __nv_bfloat16 g_xH   [NTOK * DIN],  g_xL   [NTOK * DIN];
__device__ __nv_bfloat16 g_hpreH[NTOK * DIN],  g_hpreL[NTOK * DIN];
__device__ __nv_bfloat16 g_tH   [NTOK * DOUT], g_tL   [NTOK * DOUT];
__device__ __nv_bfloat16 g_preDwTH [DIN * DIN],   g_preDwTL [DIN * DIN];   // (gamma.*W)^T
__device__ __nv_bfloat16 g_preGwTH [DIN * DIN],   g_preGwTL [DIN * DIN];
__device__ __nv_bfloat16 g_wttTH   [DOUT * DIN],  g_wttTL   [DOUT * DIN];
__device__ __nv_bfloat16 g_postDwTH[DOUT * DOUT], g_postDwTL[DOUT * DOUT]; // (gamma.*W)^T
__device__ __nv_bfloat16 g_postGwTH[DOUT * DOUT], g_postGwTL[DOUT * DOUT];

// ------------------------- helpers -----------------------------------------
__device__ __forceinline__ uint32_t smem_u32(const void* p) {
    uint32_t a;
    asm("{ .reg .u64 t; cvta.to.shared.u64 t, %1; cvt.u32.u64 %0, t; }"
        : "=r"(a) : "l"(p));
    return a;
}
__device__ __forceinline__ void cp16(uint32_t s, const void* g) {
    asm volatile("cp.async.cg.shared.global [%0], [%1], 16;" :: "r"(s), "l"(g));
}
#define CP_COMMIT() asm volatile("cp.async.commit_group;")
#define CP_WAIT1()  asm volatile("cp.async.wait_group 1;")
#define CP_WAIT0()  asm volatile("cp.async.wait_group 0;")

__device__ __forceinline__ void ldmx4(uint32_t* r, uint32_t a) {
    asm volatile("ldmatrix.sync.aligned.m8n8.x4.shared.b16 {%0,%1,%2,%3}, [%4];"
        : "=r"(r[0]), "=r"(r[1]), "=r"(r[2]), "=r"(r[3]) : "r"(a));
}
__device__ __forceinline__ void mma_bf16(float* d, const uint32_t* a, const uint32_t* b) {
    asm volatile("mma.sync.aligned.m16n8k16.row.col.f32.bf16.bf16.f32 "
        "{%0,%1,%2,%3}, {%4,%5,%6,%7}, {%8,%9}, {%0,%1,%2,%3};"
        : "+f"(d[0]), "+f"(d[1]), "+f"(d[2]), "+f"(d[3])
        : "r"(a[0]), "r"(a[1]), "r"(a[2]), "r"(a[3]), "r"(b[0]), "r"(b[1]));
}
__device__ __forceinline__ float gelu_exact(float v) {
    return 0.5f * v * (1.0f + erff(v * 0.70710678118654752f));
}
__device__ __forceinline__ float sigmoidf_(float v) {
    return 1.0f / (1.0f + __expf(-v));
}
__device__ __forceinline__ void split_bf16(float v, __nv_bfloat16& h, __nv_bfloat16& l) {
    h = __float2bfloat16_rn(v);
    l = __float2bfloat16_rn(v - __bfloat162float(h));
}

// ------------------------- row stats (mean, inv-std) [+ optional split] -----
template <int EPT, bool SPLIT>
__global__ __launch_bounds__(256) void stats_split_kernel(
    const float* __restrict__ in, float* __restrict__ muO, float* __restrict__ ivO,
    __nv_bfloat16* __restrict__ oH, __nv_bfloat16* __restrict__ oL, int D)
{
    const int row = blockIdx.x;
    const int tid = threadIdx.x;
    const float* rp = in + (size_t)row * D;

    float v[EPT];
    float s = 0.f;
#pragma unroll
    for (int e = 0; e < EPT; e++) { v[e] = rp[tid + e * 256]; s += v[e]; }

    __shared__ float red[8];
    __shared__ float sMean, sVar;
#pragma unroll
    for (int o = 16; o > 0; o >>= 1) s += __shfl_down_sync(0xffffffffu, s, o);
    if ((tid & 31) == 0) red[tid >> 5] = s;
    __syncthreads();
    if (tid < 8) {
        float w = red[tid];
#pragma unroll
        for (int o = 4; o > 0; o >>= 1) w += __shfl_down_sync(0xffu, w, o);
        if (tid == 0) sMean = w / (float)D;
    }
    __syncthreads();
    const float mean = sMean;

    float q = 0.f;
#pragma unroll
    for (int e = 0; e < EPT; e++) { float d = v[e] - mean; q += d * d; }
#pragma unroll
    for (int o = 16; o > 0; o >>= 1) q += __shfl_down_sync(0xffffffffu, q, o);
    if ((tid & 31) == 0) red[tid >> 5] = q;
    __syncthreads();
    if (tid < 8) {
        float w = red[tid];
#pragma unroll
        for (int o = 4; o > 0; o >>= 1) w += __shfl_down_sync(0xffu, w, o);
        if (tid == 0) sVar = w / (float)D;
    }
    __syncthreads();
    if (tid == 0) { muO[row] = mean; ivO[row] = rsqrtf(sVar + 1e-6f); }

    if (SPLIT) {
        const size_t rb = (size_t)row * D;
#pragma unroll
        for (int e = 0; e < EPT; e++) {
            int c = tid + e * 256;
            __nv_bfloat16 h, l;
            split_bf16(v[e], h, l);
            oH[rb + c] = h; oL[rb + c] = l;
        }
    }
}

// ------------------------- TT operator materialization ----------------------
__global__ __launch_bounds__(256) void build_a01_kernel(
    const float* __restrict__ c0, const float* __restrict__ c1,
    float* __restrict__ a01)
{
    int idx = blockIdx.x * 256 + threadIdx.x;   // 131072
    int s = idx & 15, y = (idx >> 4) & 15, b = (idx >> 8) & 7;
    int x = (idx >> 11) & 7, a = idx >> 14;
    float acc = 0.f;
#pragma unroll
    for (int r = 0; r < 16; r++)
        acc += c0[a * 128 + x * 16 + r] * c1[((r * 8 + b) * 16 + y) * 16 + s];
    a01[idx] = acc;
}

__global__ __launch_bounds__(256) void build_wttT_kernel(
    const float* __restrict__ a01, const float* __restrict__ c2,
    __nv_bfloat16* __restrict__ wH, __nv_bfloat16* __restrict__ wL)
{
    int idx = blockIdx.x * 256 + threadIdx.x;   // 4096*1024
    int in  = idx & 1023;
    int out = idx >> 10;
    int z = out & 31, y = (out >> 5) & 15, x = out >> 9;
    int c = in & 15,  b = (in >> 4) & 7,   a = in >> 7;
    const float* ap = a01 + (((a * 8 + x) * 8 + b) * 16 + y) * 16;
    float acc = 0.f;
#pragma unroll
    for (int s = 0; s < 16; s++)
        acc += ap[s] * c2[(s * 16 + c) * 32 + z];
    __nv_bfloat16 h, l;
    split_bf16(acc, h, l);
    wH[idx] = h; wL[idx] = l;
}

// ------------------------- weight transpose + split --------------------------
// out[n][k] = scale(k) * in[k][n]; SCALED multiplies by gamma[k]
template <bool SCALED>
__global__ __launch_bounds__(256) void transpose_split_kernel(
    const float* __restrict__ in, const float* __restrict__ gamma,
    __nv_bfloat16* __restrict__ oH, __nv_bfloat16* __restrict__ oL, int K, int N)
{
    __shared__ float tile[32][33];
    int n0 = blockIdx.x * 32, k0 = blockIdx.y * 32;
    int tx = threadIdx.x & 31, ty = threadIdx.x >> 5;
#pragma unroll
    for (int i = 0; i < 4; i++)
        tile[ty + i * 8][tx] = in[(size_t)(k0 + ty + i * 8) * N + n0 + tx];
    __syncthreads();
    const float gk = SCALED ? gamma[k0 + tx] : 1.f;
#pragma unroll
    for (int i = 0; i < 4; i++) {
        float v = tile[tx][ty + i * 8] * gk;
        __nv_bfloat16 h, l;
        split_bf16(v, h, l);
        size_t o = (size_t)(n0 + ty + i * 8) * K + k0 + tx;
        oH[o] = h; oL[o] = l;
    }
}

// ------------------------- column sums: gamma^T W, beta^T W ------------------
__global__ __launch_bounds__(128) void colsum_kernel(
    const float* __restrict__ W, const float* __restrict__ gamma,
    const float* __restrict__ beta, float* __restrict__ vGW,
    float* __restrict__ vBW, int K, int N)
{
    int n = blockIdx.x * 128 + threadIdx.x;
    float sg = 0.f, sb = 0.f;
#pragma unroll 4
    for (int k = 0; k < K; k++) {
        float w = W[(size_t)k * N + n];
        sg += gamma[k] * w;
        sb += beta[k] * w;
    }
    vGW[n] = sg; vBW[n] = sb;
}

// ------------------------- TT GEMM (R10 path, OP_NONE) ----------------------
__device__ __forceinline__ void load_stage4(
    uint32_t sbase,
    const __nv_bfloat16* __restrict__ Ah, const __nv_bfloat16* __restrict__ Al,
    const __nv_bfloat16* __restrict__ Bh, const __nv_bfloat16* __restrict__ Bl,
    int aRow0, int bRow0, int K, int k0, int tid)
{
#pragma unroll
    for (int i = 0; i < 2; i++) {
        int idx = tid + i * 256;
        int r = idx >> 2, c = idx & 3;
        uint32_t so = swz(r, c);
        size_t ga = (size_t)(aRow0 + r) * K + k0 + c * 8;
        size_t gb = (size_t)(bRow0 + r) * K + k0 + c * 8;
        cp16(sbase + OFF_AH + so, Ah + ga);
        cp16(sbase + OFF_AL + so, Al + ga);
        cp16(sbase + OFF_BH + so, Bh + gb);
        cp16(sbase + OFF_BL + so, Bl + gb);
    }
}

__global__ __launch_bounds__(256, 2) void tt_gemm_kernel(
    const __nv_bfloat16* __restrict__ Ah, const __nv_bfloat16* __restrict__ Al,
    const __nv_bfloat16* __restrict__ Bh, const __nv_bfloat16* __restrict__ Bl,
    float* __restrict__ CF, __nv_bfloat16* __restrict__ CH,
    __nv_bfloat16* __restrict__ CL, int M, int N, int K)
{
    extern __shared__ char smem[];
    const uint32_t sm = smem_u32(smem);
    const int tid  = threadIdx.x;
    const int lane = tid & 31;
    const int wid  = tid >> 5;
    const int blockM = blockIdx.x * BM;
    const int blockN = blockIdx.y * BN;
    const int wm = (wid >> 2) * 64;
    const int wn = (wid & 3) * 32;
    const int nk = K / BK;

    float acc[4][4][4];
#pragma unroll
    for (int i = 0; i < 4; i++)
#pragma unroll
        for (int j = 0; j < 4; j++)
#pragma unroll
            for (int e = 0; e < 4; e++) acc[i][j][e] = 0.f;

#pragma unroll
    for (int s = 0; s < STAGES - 1; s++) {
        load_stage4(sm + s * STAGE_BYTES, Ah, Al, Bh, Bl, blockM, blockN, K, s * BK, tid);
        CP_COMMIT();
    }

    const int aRow = lane & 15;
    const int aHi  = lane >> 4;
    const int bRow = wn + (lane & 7) + ((lane >> 4) << 3);
    const int bHi  = (lane >> 3) & 1;
    const int sA = ((aRow >> 1) & 3);
    const int sB = ((bRow >> 1) & 3);

    for (int t = 0; t < nk; t++) {
        CP_WAIT1();
        __syncthreads();
        const int pf = t + STAGES - 1;
        if (pf < nk)
            load_stage4(sm + (pf % STAGES) * STAGE_BYTES, Ah, Al, Bh, Bl,
                        blockM, blockN, K, pf * BK, tid);
        CP_COMMIT();

        const uint32_t sb = sm + (t % STAGES) * STAGE_BYTES;
#pragma unroll
        for (int ks = 0; ks < 2; ks++) {
            const uint32_t aChunk = (uint32_t)(((ks * 2 + aHi) ^ sA) << 4);
            const uint32_t bChunk = (uint32_t)(((ks * 2 + bHi) ^ sB) << 4);
            uint32_t ah[4][4], al[4][4];
#pragma unroll
            for (int mt = 0; mt < 4; mt++) {
                const uint32_t ra = (uint32_t)((wm + mt * 16 + aRow) * 64) + aChunk;
                ldmx4(ah[mt], sb + OFF_AH + ra);
                ldmx4(al[mt], sb + OFF_AL + ra);
            }
            const uint32_t rb = (uint32_t)(bRow * 64) + bChunk;
            uint32_t bh0[4], bl0[4];
            ldmx4(bh0, sb + OFF_BH + rb);
            ldmx4(bl0, sb + OFF_BL + rb);
#pragma unroll
            for (int mt = 0; mt < 4; mt++) mma_bf16(acc[mt][0], ah[mt], bh0 + 0);
#pragma unroll
            for (int mt = 0; mt < 4; mt++) mma_bf16(acc[mt][1], ah[mt], bh0 + 2);
#pragma unroll
            for (int mt = 0; mt < 4; mt++) mma_bf16(acc[mt][0], ah[mt], bl0 + 0);
#pragma unroll
            for (int mt = 0; mt < 4; mt++) mma_bf16(acc[mt][1], ah[mt], bl0 + 2);
#pragma unroll
            for (int mt = 0; mt < 4; mt++) mma_bf16(acc[mt][0], al[mt], bh0 + 0);
#pragma unroll
            for (int mt = 0; mt < 4; mt++) mma_bf16(acc[mt][1], al[mt], bh0 + 2);
            uint32_t bh1[4], bl1[4];
            const uint32_t rb1 = (uint32_t)((bRow + 16) * 64) + bChunk;
            ldmx4(bh1, sb + OFF_BH + rb1);
            ldmx4(bl1, sb + OFF_BL + rb1);
#pragma unroll
            for (int mt = 0; mt < 4; mt++) mma_bf16(acc[mt][2], ah[mt], bh1 + 0);
#pragma unroll
            for (int mt = 0; mt < 4; mt++) mma_bf16(acc[mt][3], ah[mt], bh1 + 2);
#pragma unroll
            for (int mt = 0; mt < 4; mt++) mma_bf16(acc[mt][2], ah[mt], bl1 + 0);
#pragma unroll
            for (int mt = 0; mt < 4; mt++) mma_bf16(acc[mt][3], ah[mt], bl1 + 2);
#pragma unroll
            for (int mt = 0; mt < 4; mt++) mma_bf16(acc[mt][2], al[mt], bh1 + 0);
#pragma unroll
            for (int mt = 0; mt < 4; mt++) mma_bf16(acc[mt][3], al[mt], bh1 + 2);
        }
    }
    CP_WAIT0();

    const int r0 = lane >> 2;
    const int c0 = (lane & 3) * 2;
#pragma unroll
    for (int mt = 0; mt < 4; mt++) {
#pragma unroll
        for (int half = 0; half < 2; half++) {
            const int m = blockM + wm + mt * 16 + r0 + half * 8;
            const size_t base = (size_t)m * N;
#pragma unroll
            for (int nt = 0; nt < 4; nt++) {
                const int n = blockN + wn + nt * 8 + c0;
                float v0 = acc[mt][nt][half * 2 + 0];
                float v1 = acc[mt][nt][half * 2 + 1];
                *(float2*)(CF + base + n) = make_float2(v0, v1);
                __nv_bfloat16 hA, lA, hB, lB;
                split_bf16(v0, hA, lA);
                split_bf16(v1, hB, lB);
                __nv_bfloat162 ph; ph.x = hA; ph.y = hB;
                __nv_bfloat162 pl; pl.x = lA; pl.y = lB;
                *(__nv_bfloat162*)(CH + base + n) = ph;
                *(__nv_bfloat162*)(CL + base + n) = pl;
            }
        }
    }
}

// ------------------------- fused dense+gate block GEMM ----------------------
// accD = A @ Bd^T (Bd = (gamma.*Wd)^T), accG = A @ Bg^T.
// d = iv*accD - mu*iv*vGW[n] + vBW[n] + db[n]; h = gelu(d)
// g = sigmoid(accG + gb[n]); out = g*h + (1-g)*R
__device__ __forceinline__ void load_stage6(
    uint32_t sbase,
    const __nv_bfloat16* __restrict__ Ah, const __nv_bfloat16* __restrict__ Al,
    const __nv_bfloat16* __restrict__ Dh, const __nv_bfloat16* __restrict__ Dl,
    const __nv_bfloat16* __restrict__ Gh, const __nv_bfloat16* __restrict__ Gl,
    int aRow0, int bRow0, int K, int k0, int tid)
{
#pragma unroll
    for (int i = 0; i < 2; i++) {
        int idx = tid + i * 256;
        int r = idx >> 2, c = idx & 3;
        uint32_t so = swz(r, c);
        size_t ga = (size_t)(aRow0 + r) * K + k0 + c * 8;
        size_t gb = (size_t)(bRow0 + r) * K + k0 + c * 8;
        cp16(sbase + F_AH + so, Ah + ga);
        cp16(sbase + F_AL + so, Al + ga);
        cp16(sbase + F_DH + so, Dh + gb);
        cp16(sbase + F_DL + so, Dl + gb);
        cp16(sbase + F_GH + so, Gh + gb);
        cp16(sbase + F_GL + so, Gl + gb);
    }
}

template <bool WF32, bool WSPLIT>
__global__ __launch_bounds__(256, 1) void fused_gemm_kernel(
    const __nv_bfloat16* __restrict__ Ah, const __nv_bfloat16* __restrict__ Al,
    const __nv_bfloat16* __restrict__ Dh, const __nv_bfloat16* __restrict__ Dl,
    const __nv_bfloat16* __restrict__ Gh, const __nv_bfloat16* __restrict__ Gl,
    const float* __restrict__ mu, const float* __restrict__ iv,
    const float* __restrict__ vGW, const float* __restrict__ vBW,
    const float* __restrict__ db, const float* __restrict__ gb,
    const float* __restrict__ R,
    float* __restrict__ CF, __nv_bfloat16* __restrict__ CH,
    __nv_bfloat16* __restrict__ CL, int M, int N, int K)
{
    extern __shared__ char smem[];
    const uint32_t sm = smem_u32(smem);
    const int tid  = threadIdx.x;
    const int lane = tid & 31;
    const int wid  = tid >> 5;
    const int blockM = blockIdx.x * BM;
    const int blockN = blockIdx.y * BN;
    const int wm = (wid >> 2) * 64;
    const int wn = (wid & 3) * 32;
    const int nk = K / BK;

    float accD[4][4][4], accG[4][4][4];
#pragma unroll
    for (int i = 0; i < 4; i++)
#pragma unroll
        for (int j = 0; j < 4; j++)
#pragma unroll
            for (int e = 0; e < 4; e++) { accD[i][j][e] = 0.f; accG[i][j][e] = 0.f; }

#pragma unroll
    for (int s = 0; s < STAGES - 1; s++) {
        load_stage6(sm + s * F_STAGE, Ah, Al, Dh, Dl, Gh, Gl,
                    blockM, blockN, K, s * BK, tid);
        CP_COMMIT();
    }

    const int aRow = lane & 15;
    const int aHi  = lane >> 4;
    const int bRow = wn + (lane & 7) + ((lane >> 4) << 3);
    const int bHi  = (lane >> 3) & 1;
    const int sA = ((aRow >> 1) & 3);
    const int sB = ((bRow >> 1) & 3);

    for (int t = 0; t < nk; t++) {
        CP_WAIT1();
        __syncthreads();
        const int pf = t + STAGES - 1;
        if (pf < nk)
            load_stage6(sm + (pf % STAGES) * F_STAGE, Ah, Al, Dh, Dl, Gh, Gl,
                        blockM, blockN, K, pf * BK, tid);
        CP_COMMIT();

        const uint32_t sb = sm + (t % STAGES) * F_STAGE;
#pragma unroll
        for (int ks = 0; ks < 2; ks++) {
            const uint32_t aChunk = (uint32_t)(((ks * 2 + aHi) ^ sA) << 4);
            const uint32_t bChunk = (uint32_t)(((ks * 2 + bHi) ^ sB) << 4);
            uint32_t ah[4][4], al[4][4];
#pragma unroll
            for (int mt = 0; mt < 4; mt++) {
                const uint32_t ra = (uint32_t)((wm + mt * 16 + aRow) * 64) + aChunk;
                ldmx4(ah[mt], sb + F_AH + ra);
                ldmx4(al[mt], sb + F_AL + ra);
            }
            const uint32_t rb  = (uint32_t)(bRow * 64) + bChunk;
            const uint32_t rb1 = (uint32_t)((bRow + 16) * 64) + bChunk;
            // ---- dense B ----
            {
                uint32_t bh0[4], bl0[4];
                ldmx4(bh0, sb + F_DH + rb);
                ldmx4(bl0, sb + F_DL + rb);
#pragma unroll
                for (int mt = 0; mt < 4; mt++) mma_bf16(accD[mt][0], ah[mt], bh0 + 0);
#pragma unroll
                for (int mt = 0; mt < 4; mt++) mma_bf16(accD[mt][1], ah[mt], bh0 + 2);
#pragma unroll
                for (int mt = 0; mt < 4; mt++) mma_bf16(accD[mt][0], ah[mt], bl0 + 0);
#pragma unroll
                for (int mt = 0; mt < 4; mt++) mma_bf16(accD[mt][1], ah[mt], bl0 + 2);
#pragma unroll
                for (int mt = 0; mt < 4; mt++) mma_bf16(accD[mt][0], al[mt], bh0 + 0);
#pragma unroll
                for (int mt = 0; mt < 4; mt++) mma_bf16(accD[mt][1], al[mt], bh0 + 2);
                uint32_t bh1[4], bl1[4];
                ldmx4(bh1, sb + F_DH + rb1);
                ldmx4(bl1, sb + F_DL + rb1);
#pragma unroll
                for (int mt = 0; mt < 4; mt++) mma_bf16(accD[mt][2], ah[mt], bh1 + 0);
#pragma unroll
                for (int mt = 0; mt < 4; mt++) mma_bf16(accD[mt][3], ah[mt], bh1 + 2);
#pragma unroll
                for (int mt = 0; mt < 4; mt++) mma_bf16(accD[mt][2], ah[mt], bl1 + 0);
#pragma unroll
                for (int mt = 0; mt < 4; mt++) mma_bf16(accD[mt][3], ah[mt], bl1 + 2);
#pragma unroll
                for (int mt = 0; mt < 4; mt++) mma_bf16(accD[mt][2], al[mt], bh1 + 0);
#pragma unroll
                for (int mt = 0; mt < 4; mt++) mma_bf16(accD[mt][3], al[mt], bh1 + 2);
            }
            // ---- gate B ----
            {
                uint32_t bh0[4], bl0[4];
                ldmx4(bh0, sb + F_GH + rb);
                ldmx4(bl0, sb + F_GL + rb);
#pragma unroll
                for (int mt = 0; mt < 4; mt++) mma_bf16(accG[mt][0], ah[mt], bh0 + 0);
#pragma unroll
                for (int mt = 0; mt < 4; mt++) mma_bf16(accG[mt][1], ah[mt], bh0 + 2);
#pragma unroll
                for (int mt = 0; mt < 4; mt++) mma_bf16(accG[mt][0], ah[mt], bl0 + 0);
#pragma unroll
                for (int mt = 0; mt < 4; mt++) mma_bf16(accG[mt][1], ah[mt], bl0 + 2);
#pragma unroll
                for (int mt = 0; mt < 4; mt++) mma_bf16(accG[mt][0], al[mt], bh0 + 0);
#pragma unroll
                for (int mt = 0; mt < 4; mt++) mma_bf16(accG[mt][1], al[mt], bh0 + 2);
                uint32_t bh1[4], bl1[4];
                ldmx4(bh1, sb + F_GH + rb1);
                ldmx4(bl1, sb + F_GL + rb1);
#pragma unroll
                for (int mt = 0; mt < 4; mt++) mma_bf16(accG[mt][2], ah[mt], bh1 + 0);
#pragma unroll
                for (int mt = 0; mt < 4; mt++) mma_bf16(accG[mt][3], ah[mt], bh1 + 2);
#pragma unroll
                for (int mt = 0; mt < 4; mt++) mma_bf16(accG[mt][2], ah[mt], bl1 + 0);
#pragma unroll
                for (int mt = 0; mt < 4; mt++) mma_bf16(accG[mt][3], ah[mt], bl1 + 2);
#pragma unroll
                for (int mt = 0; mt < 4; mt++) mma_bf16(accG[mt][2], al[mt], bh1 + 0);
#pragma unroll
                for (int mt = 0; mt < 4; mt++) mma_bf16(accG[mt][3], al[mt], bh1 + 2);
            }
        }
    }
    CP_WAIT0();

    // ---------------- epilogue ----------------
    const int r0 = lane >> 2;
    const int c0 = (lane & 3) * 2;
#pragma unroll
    for (int mt = 0; mt < 4; mt++) {
#pragma unroll
        for (int half = 0; half < 2; half++) {
            const int m = blockM + wm + mt * 16 + r0 + half * 8;
            const size_t base = (size_t)m * N;
            const float iv_m = iv[m];
            const float miv  = mu[m] * iv_m;
#pragma unroll
            for (int nt = 0; nt < 4; nt++) {
                const int n = blockN + wn + nt * 8 + c0;
                const float aD0 = accD[mt][nt][half * 2 + 0];
                const float aD1 = accD[mt][nt][half * 2 + 1];
                const float aG0 = accG[mt][nt][half * 2 + 0];
                const float aG1 = accG[mt][nt][half * 2 + 1];
                float d0 = iv_m * aD0 - miv * vGW[n]     + vBW[n]     + db[n];
                float d1 = iv_m * aD1 - miv * vGW[n + 1] + vBW[n + 1] + db[n + 1];
                float h0 = gelu_exact(d0);
                float h1 = gelu_exact(d1);
                float g0 = sigmoidf_(aG0 + gb[n]);
                float g1 = sigmoidf_(aG1 + gb[n + 1]);
                float2 rr = *(const float2*)(R + base + n);
                float v0 = g0 * h0 + (1.f - g0) * rr.x;
                float v1 = g1 * h1 + (1.f - g1) * rr.y;
                if (WF32) *(float2*)(CF + base + n) = make_float2(v0, v1);
                if (WSPLIT) {
                    __nv_bfloat16 hA, lA, hB, lB;
                    split_bf16(v0, hA, lA);
                    split_bf16(v1, hB, lB);
                    __nv_bfloat162 ph; ph.x = hA; ph.y = hB;
                    __nv_bfloat162 pl; pl.x = lA; pl.y = lB;
                    *(__nv_bfloat162*)(CH + base + n) = ph;
                    *(__nv_bfloat162*)(CL + base + n) = pl;
                }
            }
        }
    }
}

// ------------------------- launch ------------------------------------------
extern "C" void kernel_launch(void* const* d_in, const int* in_sizes, int n_in,
                              void* d_out, int out_size)
{
    const float* x      = (const float*)d_in[0];
    const float* preG   = (const float*)d_in[1];
    const float* preB   = (const float*)d_in[2];
    const float* preDw  = (const float*)d_in[3];
    const float* preDb  = (const float*)d_in[4];
    const float* preGw  = (const float*)d_in[5];
    const float* preGb  = (const float*)d_in[6];
    const float* core0  = (const float*)d_in[7];
    const float* core1  = (const float*)d_in[8];
    const float* core2  = (const float*)d_in[9];
    const float* postG  = (const float*)d_in[10];
    const float* postB  = (const float*)d_in[11];
    const float* postDw = (const float*)d_in[12];
    const float* postDb = (const float*)d_in[13];
    const float* postGw = (const float*)d_in[14];
    const float* postGb = (const float*)d_in[15];
    float* out = (float*)d_out;

    float *t, *a01, *mu1, *iv1, *mu2, *iv2, *vGW1, *vBW1, *vGW2, *vBW2;
    cudaGetSymbolAddress((void**)&t,    g_t);
    cudaGetSymbolAddress((void**)&a01,  g_a01);
    cudaGetSymbolAddress((void**)&mu1,  g_mu1);
    cudaGetSymbolAddress((void**)&iv1,  g_iv1);
    cudaGetSymbolAddress((void**)&mu2,  g_mu2);
    cudaGetSymbolAddress((void**)&iv2,  g_iv2);
    cudaGetSymbolAddress((void**)&vGW1, g_vGW1);
    cudaGetSymbolAddress((void**)&vBW1, g_vBW1);
    cudaGetSymbolAddress((void**)&vGW2, g_vGW2);
    cudaGetSymbolAddress((void**)&vBW2, g_vBW2);

    __nv_bfloat16 *xH, *xL, *hpreH, *hpreL, *tH, *tL;
    __nv_bfloat16 *preDwTH, *preDwTL, *preGwTH, *preGwTL;
    __nv_bfloat16 *wttTH, *wttTL, *postDwTH, *postDwTL, *postGwTH, *postGwTL;
    cudaGetSymbolAddress((void**)&xH,    g_xH);    cudaGetSymbolAddress((void**)&xL,    g_xL);
    cudaGetSymbolAddress((void**)&hpreH, g_hpreH); cudaGetSymbolAddress((void**)&hpreL, g_hpreL);
    cudaGetSymbolAddress((void**)&tH,    g_tH);    cudaGetSymbolAddress((void**)&tL,    g_tL);
    cudaGetSymbolAddress((void**)&preDwTH,  g_preDwTH);  cudaGetSymbolAddress((void**)&preDwTL,  g_preDwTL);
    cudaGetSymbolAddress((void**)&preGwTH,  g_preGwTH);  cudaGetSymbolAddress((void**)&preGwTL,  g_preGwTL);
    cudaGetSymbolAddress((void**)&wttTH,    g_wttTH);    cudaGetSymbolAddress((void**)&wttTL,    g_wttTL);
    cudaGetSymbolAddress((void**)&postDwTH, g_postDwTH); cudaGetSymbolAddress((void**)&postDwTL, g_postDwTL);
    cudaGetSymbolAddress((void**)&postGwTH, g_postGwTH); cudaGetSymbolAddress((void**)&postGwTL, g_postGwTL);

    cudaFuncSetAttribute(tt_gemm_kernel,
                         cudaFuncAttributeMaxDynamicSharedMemorySize, GEMM_SMEM);
    cudaFuncSetAttribute(fused_gemm_kernel<false, true>,
                         cudaFuncAttributeMaxDynamicSharedMemorySize, F_SMEM);
    cudaFuncSetAttribute(fused_gemm_kernel<true, false>,
                         cudaFuncAttributeMaxDynamicSharedMemorySize, F_SMEM);

    // --- operator prep (independent of x) ---
    build_a01_kernel<<<131072 / 256, 256>>>(core0, core1, a01);
    build_wttT_kernel<<<(DIN * DOUT) / 256, 256>>>(a01, core2, wttTH, wttTL);
    transpose_split_kernel<true ><<<dim3(DIN / 32, DIN / 32), 256>>>(preDw, preG, preDwTH, preDwTL, DIN, DIN);
    transpose_split_kernel<false><<<dim3(DIN / 32, DIN / 32), 256>>>(preGw, nullptr, preGwTH, preGwTL, DIN, DIN);
    transpose_split_kernel<true ><<<dim3(DOUT / 32, DOUT / 32), 256>>>(postDw, postG, postDwTH, postDwTL, DOUT, DOUT);
    transpose_split_kernel<false><<<dim3(DOUT / 32, DOUT / 32), 256>>>(postGw, nullptr, postGwTH, postGwTL, DOUT, DOUT);
    colsum_kernel<<<DIN / 128, 128>>>(preDw, preG, preB, vGW1, vBW1, DIN, DIN);
    colsum_kernel<<<DOUT / 128, 128>>>(postDw, postG, postB, vGW2, vBW2, DOUT, DOUT);

    // --- pre block: stats + fused dense/gate ---
    stats_split_kernel<DIN / 256, true><<<NTOK, 256>>>(x, mu1, iv1, xH, xL, DIN);
    fused_gemm_kernel<false, true><<<dim3(NTOK / BM, DIN / BN), 256, F_SMEM>>>(
        xH, xL, preDwTH, preDwTL, preGwTH, preGwTL,
        mu1, iv1, vGW1, vBW1, preDb, preGb, x,
        nullptr, hpreH, hpreL, NTOK, DIN, DIN);

    // --- TT contraction ---
    tt_gemm_kernel<<<dim3(NTOK / BM, DOUT / BN), 256, GEMM_SMEM>>>(
        hpreH, hpreL, wttTH, wttTL, t, tH, tL, NTOK, DOUT, DIN);

    // --- post block: stats + fused dense/gate ---
    stats_split_kernel<DOUT / 256, false><<<NTOK, 256>>>(t, mu2, iv2, nullptr, nullptr, DOUT);
    fused_gemm_kernel<true, false><<<dim3(NTOK / BM, DOUT / BN), 256, F_SMEM>>>(
        tH, tL, postDwTH, postDwTL, postGwTH, postGwTL,
        mu2, iv2, vGW2, vBW2, postDb, postGb, t,
        out, nullptr, nullptr, NTOK, DOUT, DOUT);
}

// round 12
// speedup vs baseline: 1.5635x; 1.5635x over previous
#include <cuda_runtime.h>
#include <cuda_bf16.h>
#include <math.h>
#include <stdint.h>

// ---------------------------------------------------------------------------
// HybridTTLayer via mma.sync bf16 tensor cores (plain sm_100 target).
// fp32 emulated as bf16 hi+lo split, 3-product MMA.
// R12 = R10 (best: 2677us) + post-block dense/gate GEMMs merged into ONE
// launch via gridDim.z (kills the 4-wave quantization tail; 2048 CTAs -> 7
// waves @ 98.8%), with a streaming combine kernel for the gated residual.
// Pre block keeps the R10 fused-gate path (single-wave launches already).
// ---------------------------------------------------------------------------

#define NTOK   4096
#define DIN    1024
#define DOUT   4096

#define OP_NONE 0
#define OP_GELU 1
#define OP_GATE 2

// GEMM tiling
#define BM 128
#define BN 128
#define BK 32
#define STAGES 3
#define OFF_AH 0
#define OFF_AL 8192
#define OFF_BH 16384
#define OFF_BL 24576
#define STAGE_BYTES 32768
#define GEMM_SMEM (STAGES * STAGE_BYTES)   // 98304 -> 2 CTAs/SM

// swizzled byte offset of 16B chunk c (0..3) in row r (64B rows)
__device__ __forceinline__ uint32_t swz(int r, int c) {
    return (uint32_t)(r * 64 + ((c ^ ((r >> 1) & 3)) << 4));
}

// ------------------------- scratch (static device memory) ------------------
__device__ float g_h1 [NTOK * DIN];
__device__ float g_t  [NTOK * DOUT];
__device__ float g_h2 [NTOK * DOUT];
__device__ float g_gb [NTOK * DOUT];      // post gate sigmoid buffer
__device__ float g_a01[8 * 8 * 8 * 16 * 16];
__device__ __nv_bfloat16 g_xH   [NTOK * DIN],  g_xL   [NTOK * DIN];
__device__ __nv_bfloat16 g_ln1H [NTOK * DIN],  g_ln1L [NTOK * DIN];
__device__ __nv_bfloat16 g_hpreH[NTOK * DIN],  g_hpreL[NTOK * DIN];
__device__ __nv_bfloat16 g_tH   [NTOK * DOUT], g_tL   [NTOK * DOUT];
__device__ __nv_bfloat16 g_ln2H [NTOK * DOUT], g_ln2L [NTOK * DOUT];
__device__ __nv_bfloat16 g_preDwTH [DIN * DIN],   g_preDwTL [DIN * DIN];
__device__ __nv_bfloat16 g_preGwTH [DIN * DIN],   g_preGwTL [DIN * DIN];
__device__ __nv_bfloat16 g_wttTH   [DOUT * DIN],  g_wttTL   [DOUT * DIN];
__device__ __nv_bfloat16 g_postDwTH[DOUT * DOUT], g_postDwTL[DOUT * DOUT];
__device__ __nv_bfloat16 g_postGwTH[DOUT * DOUT], g_postGwTL[DOUT * DOUT];

// ------------------------- helpers -----------------------------------------
__device__ __forceinline__ uint32_t smem_u32(const void* p) {
    uint32_t a;
    asm("{ .reg .u64 t; cvta.to.shared.u64 t, %1; cvt.u32.u64 %0, t; }"
        : "=r"(a) : "l"(p));
    return a;
}
__device__ __forceinline__ void cp16(uint32_t s, const void* g) {
    asm volatile("cp.async.cg.shared.global [%0], [%1], 16;" :: "r"(s), "l"(g));
}
#define CP_COMMIT() asm volatile("cp.async.commit_group;")
#define CP_WAIT1()  asm volatile("cp.async.wait_group 1;")
#define CP_WAIT0()  asm volatile("cp.async.wait_group 0;")

__device__ __forceinline__ void ldmx4(uint32_t* r, uint32_t a) {
    asm volatile("ldmatrix.sync.aligned.m8n8.x4.shared.b16 {%0,%1,%2,%3}, [%4];"
        : "=r"(r[0]), "=r"(r[1]), "=r"(r[2]), "=r"(r[3]) : "r"(a));
}
__device__ __forceinline__ void mma_bf16(float* d, const uint32_t* a, const uint32_t* b) {
    asm volatile("mma.sync.aligned.m16n8k16.row.col.f32.bf16.bf16.f32 "
        "{%0,%1,%2,%3}, {%4,%5,%6,%7}, {%8,%9}, {%0,%1,%2,%3};"
        : "+f"(d[0]), "+f"(d[1]), "+f"(d[2]), "+f"(d[3])
        : "r"(a[0]), "r"(a[1]), "r"(a[2]), "r"(a[3]), "r"(b[0]), "r"(b[1]));
}
__device__ __forceinline__ float gelu_exact(float v) {
    return 0.5f * v * (1.0f + erff(v * 0.70710678118654752f));
}
__device__ __forceinline__ float sigmoidf_(float v) {
    return 1.0f / (1.0f + __expf(-v));
}
__device__ __forceinline__ void split_bf16(float v, __nv_bfloat16& h, __nv_bfloat16& l) {
    h = __float2bfloat16_rn(v);
    l = __float2bfloat16_rn(v - __bfloat162float(h));
}

// ------------------------- layernorm (emits bf16 hi/lo) ----------------------
template <int EPT, bool SPLIT_IN>
__global__ __launch_bounds__(256) void layernorm_split_kernel(
    const float* __restrict__ in, const float* __restrict__ gamma,
    const float* __restrict__ beta,
    __nv_bfloat16* __restrict__ oH, __nv_bfloat16* __restrict__ oL,
    __nv_bfloat16* __restrict__ iH, __nv_bfloat16* __restrict__ iL, int D)
{
    const int row = blockIdx.x;
    const int tid = threadIdx.x;
    const float* rp = in + (size_t)row * D;

    float v[EPT];
    float s = 0.f;
#pragma unroll
    for (int e = 0; e < EPT; e++) { v[e] = rp[tid + e * 256]; s += v[e]; }

    __shared__ float red[8];
    __shared__ float sMean, sVar;
#pragma unroll
    for (int o = 16; o > 0; o >>= 1) s += __shfl_down_sync(0xffffffffu, s, o);
    if ((tid & 31) == 0) red[tid >> 5] = s;
    __syncthreads();
    if (tid < 8) {
        float w = red[tid];
#pragma unroll
        for (int o = 4; o > 0; o >>= 1) w += __shfl_down_sync(0xffu, w, o);
        if (tid == 0) sMean = w / (float)D;
    }
    __syncthreads();
    const float mean = sMean;

    float q = 0.f;
#pragma unroll
    for (int e = 0; e < EPT; e++) { float d = v[e] - mean; q += d * d; }
#pragma unroll
    for (int o = 16; o > 0; o >>= 1) q += __shfl_down_sync(0xffffffffu, q, o);
    if ((tid & 31) == 0) red[tid >> 5] = q;
    __syncthreads();
    if (tid < 8) {
        float w = red[tid];
#pragma unroll
        for (int o = 4; o > 0; o >>= 1) w += __shfl_down_sync(0xffu, w, o);
        if (tid == 0) sVar = w / (float)D;
    }
    __syncthreads();
    const float inv = rsqrtf(sVar + 1e-6f);

    const size_t rb = (size_t)row * D;
#pragma unroll
    for (int e = 0; e < EPT; e++) {
        int c = tid + e * 256;
        float o = (v[e] - mean) * inv * gamma[c] + beta[c];
        __nv_bfloat16 h, l;
        split_bf16(o, h, l);
        oH[rb + c] = h; oL[rb + c] = l;
        if (SPLIT_IN) {
            split_bf16(v[e], h, l);
            iH[rb + c] = h; iL[rb + c] = l;
        }
    }
}

// ------------------------- TT operator materialization ----------------------
__global__ __launch_bounds__(256) void build_a01_kernel(
    const float* __restrict__ c0, const float* __restrict__ c1,
    float* __restrict__ a01)
{
    int idx = blockIdx.x * 256 + threadIdx.x;   // 131072
    int s = idx & 15, y = (idx >> 4) & 15, b = (idx >> 8) & 7;
    int x = (idx >> 11) & 7, a = idx >> 14;
    float acc = 0.f;
#pragma unroll
    for (int r = 0; r < 16; r++)
        acc += c0[a * 128 + x * 16 + r] * c1[((r * 8 + b) * 16 + y) * 16 + s];
    a01[idx] = acc;
}

__global__ __launch_bounds__(256) void build_wttT_kernel(
    const float* __restrict__ a01, const float* __restrict__ c2,
    __nv_bfloat16* __restrict__ wH, __nv_bfloat16* __restrict__ wL)
{
    int idx = blockIdx.x * 256 + threadIdx.x;   // 4096*1024
    int in  = idx & 1023;
    int out = idx >> 10;
    int z = out & 31, y = (out >> 5) & 15, x = out >> 9;
    int c = in & 15,  b = (in >> 4) & 7,   a = in >> 7;
    const float* ap = a01 + (((a * 8 + x) * 8 + b) * 16 + y) * 16;
    float acc = 0.f;
#pragma unroll
    for (int s = 0; s < 16; s++)
        acc += ap[s] * c2[(s * 16 + c) * 32 + z];
    __nv_bfloat16 h, l;
    split_bf16(acc, h, l);
    wH[idx] = h; wL[idx] = l;
}

// ------------------------- weight transpose + split --------------------------
__global__ __launch_bounds__(256) void transpose_split_kernel(
    const float* __restrict__ in, __nv_bfloat16* __restrict__ oH,
    __nv_bfloat16* __restrict__ oL, int K, int N)
{
    __shared__ float tile[32][33];
    int n0 = blockIdx.x * 32, k0 = blockIdx.y * 32;
    int tx = threadIdx.x & 31, ty = threadIdx.x >> 5;
#pragma unroll
    for (int i = 0; i < 4; i++)
        tile[ty + i * 8][tx] = in[(size_t)(k0 + ty + i * 8) * N + n0 + tx];
    __syncthreads();
#pragma unroll
    for (int i = 0; i < 4; i++) {
        float v = tile[tx][ty + i * 8];
        __nv_bfloat16 h, l;
        split_bf16(v, h, l);
        size_t o = (size_t)(n0 + ty + i * 8) * K + k0 + tx;
        oH[o] = h; oL[o] = l;
    }
}

// ------------------------- streaming combine: out = g*h + (1-g)*r -----------
__global__ __launch_bounds__(256) void combine_kernel(
    const float* __restrict__ g, const float* __restrict__ h,
    const float* __restrict__ r, float* __restrict__ out, int n4)
{
    int i = blockIdx.x * 256 + threadIdx.x;
    if (i < n4) {
        float4 gv = ((const float4*)g)[i];
        float4 hv = ((const float4*)h)[i];
        float4 rv = ((const float4*)r)[i];
        float4 o;
        o.x = gv.x * hv.x + (1.f - gv.x) * rv.x;
        o.y = gv.y * hv.y + (1.f - gv.y) * rv.y;
        o.z = gv.z * hv.z + (1.f - gv.z) * rv.z;
        o.w = gv.w * hv.w + (1.f - gv.w) * rv.w;
        ((float4*)out)[i] = o;
    }
}

// ------------------------- core mainloop (shared) ----------------------------
__device__ __forceinline__ void load_stage4(
    uint32_t sbase,
    const __nv_bfloat16* __restrict__ Ah, const __nv_bfloat16* __restrict__ Al,
    const __nv_bfloat16* __restrict__ Bh, const __nv_bfloat16* __restrict__ Bl,
    int aRow0, int bRow0, int K, int k0, int tid)
{
#pragma unroll
    for (int i = 0; i < 2; i++) {
        int idx = tid + i * 256;
        int r = idx >> 2, c = idx & 3;
        uint32_t so = swz(r, c);
        size_t ga = (size_t)(aRow0 + r) * K + k0 + c * 8;
        size_t gb = (size_t)(bRow0 + r) * K + k0 + c * 8;
        cp16(sbase + OFF_AH + so, Ah + ga);
        cp16(sbase + OFF_AL + so, Al + ga);
        cp16(sbase + OFF_BH + so, Bh + gb);
        cp16(sbase + OFF_BL + so, Bl + gb);
    }
}

// mainloop producing acc[4][4][4] for one 128x128 tile
__device__ __forceinline__ void gemm_mainloop(
    uint32_t sm, float acc[4][4][4],
    const __nv_bfloat16* __restrict__ Ah, const __nv_bfloat16* __restrict__ Al,
    const __nv_bfloat16* __restrict__ Bh, const __nv_bfloat16* __restrict__ Bl,
    int blockM, int blockN, int K, int tid, int lane, int wm, int wn)
{
    const int nk = K / BK;
#pragma unroll
    for (int s = 0; s < STAGES - 1; s++) {
        load_stage4(sm + s * STAGE_BYTES, Ah, Al, Bh, Bl, blockM, blockN, K, s * BK, tid);
        CP_COMMIT();
    }
    const int aRow = lane & 15;
    const int aHi  = lane >> 4;
    const int bRow = wn + (lane & 7) + ((lane >> 4) << 3);
    const int bHi  = (lane >> 3) & 1;
    const int sA = ((aRow >> 1) & 3);
    const int sB = ((bRow >> 1) & 3);

    for (int t = 0; t < nk; t++) {
        CP_WAIT1();
        __syncthreads();
        const int pf = t + STAGES - 1;
        if (pf < nk)
            load_stage4(sm + (pf % STAGES) * STAGE_BYTES, Ah, Al, Bh, Bl,
                        blockM, blockN, K, pf * BK, tid);
        CP_COMMIT();

        const uint32_t sb = sm + (t % STAGES) * STAGE_BYTES;
#pragma unroll
        for (int ks = 0; ks < 2; ks++) {
            const uint32_t aChunk = (uint32_t)(((ks * 2 + aHi) ^ sA) << 4);
            const uint32_t bChunk = (uint32_t)(((ks * 2 + bHi) ^ sB) << 4);
            uint32_t ah[4][4], al[4][4];
#pragma unroll
            for (int mt = 0; mt < 4; mt++) {
                const uint32_t ra = (uint32_t)((wm + mt * 16 + aRow) * 64) + aChunk;
                ldmx4(ah[mt], sb + OFF_AH + ra);
                ldmx4(al[mt], sb + OFF_AL + ra);
            }
            const uint32_t rb = (uint32_t)(bRow * 64) + bChunk;
            uint32_t bh0[4], bl0[4];
            ldmx4(bh0, sb + OFF_BH + rb);
            ldmx4(bl0, sb + OFF_BL + rb);
#pragma unroll
            for (int mt = 0; mt < 4; mt++) mma_bf16(acc[mt][0], ah[mt], bh0 + 0);
#pragma unroll
            for (int mt = 0; mt < 4; mt++) mma_bf16(acc[mt][1], ah[mt], bh0 + 2);
#pragma unroll
            for (int mt = 0; mt < 4; mt++) mma_bf16(acc[mt][0], ah[mt], bl0 + 0);
#pragma unroll
            for (int mt = 0; mt < 4; mt++) mma_bf16(acc[mt][1], ah[mt], bl0 + 2);
#pragma unroll
            for (int mt = 0; mt < 4; mt++) mma_bf16(acc[mt][0], al[mt], bh0 + 0);
#pragma unroll
            for (int mt = 0; mt < 4; mt++) mma_bf16(acc[mt][1], al[mt], bh0 + 2);
            uint32_t bh1[4], bl1[4];
            const uint32_t rb1 = (uint32_t)((bRow + 16) * 64) + bChunk;
            ldmx4(bh1, sb + OFF_BH + rb1);
            ldmx4(bl1, sb + OFF_BL + rb1);
#pragma unroll
            for (int mt = 0; mt < 4; mt++) mma_bf16(acc[mt][2], ah[mt], bh1 + 0);
#pragma unroll
            for (int mt = 0; mt < 4; mt++) mma_bf16(acc[mt][3], ah[mt], bh1 + 2);
#pragma unroll
            for (int mt = 0; mt < 4; mt++) mma_bf16(acc[mt][2], ah[mt], bl1 + 0);
#pragma unroll
            for (int mt = 0; mt < 4; mt++) mma_bf16(acc[mt][3], ah[mt], bl1 + 2);
#pragma unroll
            for (int mt = 0; mt < 4; mt++) mma_bf16(acc[mt][2], al[mt], bh1 + 0);
#pragma unroll
            for (int mt = 0; mt < 4; mt++) mma_bf16(acc[mt][3], al[mt], bh1 + 2);
        }
    }
    CP_WAIT0();
}

// ------------------------- R10 GEMM (pre block + TT) ------------------------
template <int OP>
__device__ __forceinline__ float epi_op(float acc, float b, float h, float r) {
    if (OP == OP_GELU) return gelu_exact(acc + b);
    if (OP == OP_GATE) { float g = sigmoidf_(acc + b); return g * h + (1.f - g) * r; }
    return acc;
}

template <int OP, bool WF32, bool WSPLIT>
__global__ __launch_bounds__(256, 2) void mma_gemm_kernel(
    const __nv_bfloat16* __restrict__ Ah, const __nv_bfloat16* __restrict__ Al,
    const __nv_bfloat16* __restrict__ Bh, const __nv_bfloat16* __restrict__ Bl,
    const float* __restrict__ bias, const float* __restrict__ Hm,
    const float* __restrict__ Rm,
    float* __restrict__ CF, __nv_bfloat16* __restrict__ CH,
    __nv_bfloat16* __restrict__ CL, int M, int N, int K)
{
    extern __shared__ char smem[];
    const uint32_t sm = smem_u32(smem);
    const int tid  = threadIdx.x;
    const int lane = tid & 31;
    const int wid  = tid >> 5;
    const int blockM = blockIdx.x * BM;
    const int blockN = blockIdx.y * BN;
    const int wm = (wid >> 2) * 64;
    const int wn = (wid & 3) * 32;

    float acc[4][4][4];
#pragma unroll
    for (int i = 0; i < 4; i++)
#pragma unroll
        for (int j = 0; j < 4; j++)
#pragma unroll
            for (int e = 0; e < 4; e++) acc[i][j][e] = 0.f;

    gemm_mainloop(sm, acc, Ah, Al, Bh, Bl, blockM, blockN, K, tid, lane, wm, wn);

    const int r0 = lane >> 2;
    const int c0 = (lane & 3) * 2;
#pragma unroll
    for (int mt = 0; mt < 4; mt++) {
#pragma unroll
        for (int half = 0; half < 2; half++) {
            const int m = blockM + wm + mt * 16 + r0 + half * 8;
            const size_t base = (size_t)m * N;
#pragma unroll
            for (int nt = 0; nt < 4; nt++) {
                const int n = blockN + wn + nt * 8 + c0;
                float v0 = acc[mt][nt][half * 2 + 0];
                float v1 = acc[mt][nt][half * 2 + 1];
                float b0 = 0.f, b1 = 0.f, h0 = 0.f, h1 = 0.f, rr0 = 0.f, rr1 = 0.f;
                if (OP != OP_NONE) { b0 = bias[n]; b1 = bias[n + 1]; }
                if (OP == OP_GATE) {
                    float2 hh = *(const float2*)(Hm + base + n);
                    float2 rr = *(const float2*)(Rm + base + n);
                    h0 = hh.x; h1 = hh.y; rr0 = rr.x; rr1 = rr.y;
                }
                v0 = epi_op<OP>(v0, b0, h0, rr0);
                v1 = epi_op<OP>(v1, b1, h1, rr1);
                if (WF32) *(float2*)(CF + base + n) = make_float2(v0, v1);
                if (WSPLIT) {
                    __nv_bfloat16 hA, lA, hB, lB;
                    split_bf16(v0, hA, lA);
                    split_bf16(v1, hB, lB);
                    __nv_bfloat162 ph; ph.x = hA; ph.y = hB;
                    __nv_bfloat162 pl; pl.x = lA; pl.y = lB;
                    *(__nv_bfloat162*)(CH + base + n) = ph;
                    *(__nv_bfloat162*)(CL + base + n) = pl;
                }
            }
        }
    }
}

// ------------------------- merged post GEMM (z selects dense/gate) ----------
// z=0: A=ln2 split, B=postDw -> h2 = gelu(acc + db)
// z=1: A=t   split, B=postGw -> g  = sigmoid(acc + gb)
__global__ __launch_bounds__(256, 2) void post_merged_kernel(
    const __nv_bfloat16* __restrict__ AdH, const __nv_bfloat16* __restrict__ AdL,
    const __nv_bfloat16* __restrict__ BdH, const __nv_bfloat16* __restrict__ BdL,
    const __nv_bfloat16* __restrict__ AgH, const __nv_bfloat16* __restrict__ AgL,
    const __nv_bfloat16* __restrict__ BgH, const __nv_bfloat16* __restrict__ BgL,
    const float* __restrict__ db, const float* __restrict__ gbv,
    float* __restrict__ h2, float* __restrict__ gbuf, int M, int N, int K)
{
    extern __shared__ char smem[];
    const uint32_t sm = smem_u32(smem);
    const int tid  = threadIdx.x;
    const int lane = tid & 31;
    const int wid  = tid >> 5;
    const int blockM = blockIdx.x * BM;
    const int blockN = blockIdx.y * BN;
    const int z = blockIdx.z;
    const int wm = (wid >> 2) * 64;
    const int wn = (wid & 3) * 32;

    const __nv_bfloat16* Ah = z ? AgH : AdH;
    const __nv_bfloat16* Al = z ? AgL : AdL;
    const __nv_bfloat16* Bh = z ? BgH : BdH;
    const __nv_bfloat16* Bl = z ? BgL : BdL;
    const float* bias = z ? gbv : db;
    float* CF = z ? gbuf : h2;

    float acc[4][4][4];
#pragma unroll
    for (int i = 0; i < 4; i++)
#pragma unroll
        for (int j = 0; j < 4; j++)
#pragma unroll
            for (int e = 0; e < 4; e++) acc[i][j][e] = 0.f;

    gemm_mainloop(sm, acc, Ah, Al, Bh, Bl, blockM, blockN, K, tid, lane, wm, wn);

    const int r0 = lane >> 2;
    const int c0 = (lane & 3) * 2;
#pragma unroll
    for (int mt = 0; mt < 4; mt++) {
#pragma unroll
        for (int half = 0; half < 2; half++) {
            const int m = blockM + wm + mt * 16 + r0 + half * 8;
            const size_t base = (size_t)m * N;
#pragma unroll
            for (int nt = 0; nt < 4; nt++) {
                const int n = blockN + wn + nt * 8 + c0;
                float v0 = acc[mt][nt][half * 2 + 0] + bias[n];
                float v1 = acc[mt][nt][half * 2 + 1] + bias[n + 1];
                if (z == 0) { v0 = gelu_exact(v0); v1 = gelu_exact(v1); }
                else        { v0 = sigmoidf_(v0);  v1 = sigmoidf_(v1);  }
                *(float2*)(CF + base + n) = make_float2(v0, v1);
            }
        }
    }
}

// ------------------------- launch ------------------------------------------
extern "C" void kernel_launch(void* const* d_in, const int* in_sizes, int n_in,
                              void* d_out, int out_size)
{
    const float* x      = (const float*)d_in[0];
    const float* preG   = (const float*)d_in[1];
    const float* preB   = (const float*)d_in[2];
    const float* preDw  = (const float*)d_in[3];
    const float* preDb  = (const float*)d_in[4];
    const float* preGw  = (const float*)d_in[5];
    const float* preGb  = (const float*)d_in[6];
    const float* core0  = (const float*)d_in[7];
    const float* core1  = (const float*)d_in[8];
    const float* core2  = (const float*)d_in[9];
    const float* postG  = (const float*)d_in[10];
    const float* postB  = (const float*)d_in[11];
    const float* postDw = (const float*)d_in[12];
    const float* postDb = (const float*)d_in[13];
    const float* postGw = (const float*)d_in[14];
    const float* postGb = (const float*)d_in[15];
    float* out = (float*)d_out;

    float *h1, *t, *h2, *gbuf, *a01;
    cudaGetSymbolAddress((void**)&h1,   g_h1);
    cudaGetSymbolAddress((void**)&t,    g_t);
    cudaGetSymbolAddress((void**)&h2,   g_h2);
    cudaGetSymbolAddress((void**)&gbuf, g_gb);
    cudaGetSymbolAddress((void**)&a01,  g_a01);

    __nv_bfloat16 *xH, *xL, *ln1H, *ln1L, *hpreH, *hpreL, *tH, *tL, *ln2H, *ln2L;
    __nv_bfloat16 *preDwTH, *preDwTL, *preGwTH, *preGwTL;
    __nv_bfloat16 *wttTH, *wttTL, *postDwTH, *postDwTL, *postGwTH, *postGwTL;
    cudaGetSymbolAddress((void**)&xH,    g_xH);    cudaGetSymbolAddress((void**)&xL,    g_xL);
    cudaGetSymbolAddress((void**)&ln1H,  g_ln1H);  cudaGetSymbolAddress((void**)&ln1L,  g_ln1L);
    cudaGetSymbolAddress((void**)&hpreH, g_hpreH); cudaGetSymbolAddress((void**)&hpreL, g_hpreL);
    cudaGetSymbolAddress((void**)&tH,    g_tH);    cudaGetSymbolAddress((void**)&tL,    g_tL);
    cudaGetSymbolAddress((void**)&ln2H,  g_ln2H);  cudaGetSymbolAddress((void**)&ln2L,  g_ln2L);
    cudaGetSymbolAddress((void**)&preDwTH,  g_preDwTH);  cudaGetSymbolAddress((void**)&preDwTL,  g_preDwTL);
    cudaGetSymbolAddress((void**)&preGwTH,  g_preGwTH);  cudaGetSymbolAddress((void**)&preGwTL,  g_preGwTL);
    cudaGetSymbolAddress((void**)&wttTH,    g_wttTH);    cudaGetSymbolAddress((void**)&wttTL,    g_wttTL);
    cudaGetSymbolAddress((void**)&postDwTH, g_postDwTH); cudaGetSymbolAddress((void**)&postDwTL, g_postDwTL);
    cudaGetSymbolAddress((void**)&postGwTH, g_postGwTH); cudaGetSymbolAddress((void**)&postGwTL, g_postGwTL);

    cudaFuncSetAttribute(mma_gemm_kernel<OP_GELU, true, false>,
                         cudaFuncAttributeMaxDynamicSharedMemorySize, GEMM_SMEM);
    cudaFuncSetAttribute(mma_gemm_kernel<OP_GATE, false, true>,
                         cudaFuncAttributeMaxDynamicSharedMemorySize, GEMM_SMEM);
    cudaFuncSetAttribute(mma_gemm_kernel<OP_NONE, true, true>,
                         cudaFuncAttributeMaxDynamicSharedMemorySize, GEMM_SMEM);
    cudaFuncSetAttribute(post_merged_kernel,
                         cudaFuncAttributeMaxDynamicSharedMemorySize, GEMM_SMEM);

    // --- operator prep (independent of x) ---
    build_a01_kernel<<<131072 / 256, 256>>>(core0, core1, a01);
    build_wttT_kernel<<<(DIN * DOUT) / 256, 256>>>(a01, core2, wttTH, wttTL);
    transpose_split_kernel<<<dim3(DIN / 32, DIN / 32), 256>>>(preDw, preDwTH, preDwTL, DIN, DIN);
    transpose_split_kernel<<<dim3(DIN / 32, DIN / 32), 256>>>(preGw, preGwTH, preGwTL, DIN, DIN);
    transpose_split_kernel<<<dim3(DOUT / 32, DOUT / 32), 256>>>(postDw, postDwTH, postDwTL, DOUT, DOUT);
    transpose_split_kernel<<<dim3(DOUT / 32, DOUT / 32), 256>>>(postGw, postGwTH, postGwTL, DOUT, DOUT);

    // --- pre block (R10 path) ---
    layernorm_split_kernel<DIN / 256, true><<<NTOK, 256>>>(
        x, preG, preB, ln1H, ln1L, xH, xL, DIN);
    mma_gemm_kernel<OP_GELU, true, false><<<dim3(NTOK / BM, DIN / BN), 256, GEMM_SMEM>>>(
        ln1H, ln1L, preDwTH, preDwTL, preDb, nullptr, nullptr,
        h1, nullptr, nullptr, NTOK, DIN, DIN);
    mma_gemm_kernel<OP_GATE, false, true><<<dim3(NTOK / BM, DIN / BN), 256, GEMM_SMEM>>>(
        xH, xL, preGwTH, preGwTL, preGb, h1, x,
        nullptr, hpreH, hpreL, NTOK, DIN, DIN);

    // --- TT contraction ---
    mma_gemm_kernel<OP_NONE, true, true><<<dim3(NTOK / BM, DOUT / BN), 256, GEMM_SMEM>>>(
        hpreH, hpreL, wttTH, wttTL, nullptr, nullptr, nullptr,
        t, tH, tL, NTOK, DOUT, DIN);

    // --- post block: LN, merged dense+gate (z), streaming combine ---
    layernorm_split_kernel<DOUT / 256, false><<<NTOK, 256>>>(
        t, postG, postB, ln2H, ln2L, nullptr, nullptr, DOUT);
    post_merged_kernel<<<dim3(NTOK / BM, DOUT / BN, 2), 256, GEMM_SMEM>>>(
        ln2H, ln2L, postDwTH, postDwTL,
        tH, tL, postGwTH, postGwTL,
        postDb, postGb, h2, gbuf, NTOK, DOUT, DOUT);
    combine_kernel<<<(NTOK * DOUT / 4 + 255) / 256, 256>>>(
        gbuf, h2, t, out, NTOK * DOUT / 4);
}

// round 13
// speedup vs baseline: 1.6744x; 1.0709x over previous
#include <cuda_runtime.h>
#include <cuda_bf16.h>
#include <math.h>
#include <stdint.h>

// ---------------------------------------------------------------------------
// HybridTTLayer via mma.sync bf16 tensor cores (plain sm_100 target).
// fp32 emulated as bf16 hi+lo split, 3-product MMA.
// R13 = R12 structure + GEMM rebuilt for smem-crossbar relief:
//   CTA 128x128 with 128 threads (4 warps), warp tile 64x64 (2x2 grid),
//   BK=32, 3-stage cp.async, 2 CTAs/SM. LDSM bytes/MMA cut 33%.
// ---------------------------------------------------------------------------

#define NTOK   4096
#define DIN    1024
#define DOUT   4096

#define OP_NONE 0
#define OP_GELU 1
#define OP_GATE 2

// GEMM tiling
#define BM 128
#define BN 128
#define BK 32
#define NTHR 128
#define STAGES 3
#define OFF_AH 0
#define OFF_AL 8192
#define OFF_BH 16384
#define OFF_BL 24576
#define STAGE_BYTES 32768
#define GEMM_SMEM (STAGES * STAGE_BYTES)   // 98304 -> 2 CTAs/SM

// swizzled byte offset of 16B chunk c (0..3) in row r (64B rows)
__device__ __forceinline__ uint32_t swz(int r, int c) {
    return (uint32_t)(r * 64 + ((c ^ ((r >> 1) & 3)) << 4));
}

// ------------------------- scratch (static device memory) ------------------
__device__ float g_h1 [NTOK * DIN];
__device__ float g_t  [NTOK * DOUT];
__device__ float g_h2 [NTOK * DOUT];
__device__ float g_gb [NTOK * DOUT];      // post gate sigmoid buffer
__device__ float g_a01[8 * 8 * 8 * 16 * 16];
__device__ __nv_bfloat16 g_xH   [NTOK * DIN],  g_xL   [NTOK * DIN];
__device__ __nv_bfloat16 g_ln1H [NTOK * DIN],  g_ln1L [NTOK * DIN];
__device__ __nv_bfloat16 g_hpreH[NTOK * DIN],  g_hpreL[NTOK * DIN];
__device__ __nv_bfloat16 g_tH   [NTOK * DOUT], g_tL   [NTOK * DOUT];
__device__ __nv_bfloat16 g_ln2H [NTOK * DOUT], g_ln2L [NTOK * DOUT];
__device__ __nv_bfloat16 g_preDwTH [DIN * DIN],   g_preDwTL [DIN * DIN];
__device__ __nv_bfloat16 g_preGwTH [DIN * DIN],   g_preGwTL [DIN * DIN];
__device__ __nv_bfloat16 g_wttTH   [DOUT * DIN],  g_wttTL   [DOUT * DIN];
__device__ __nv_bfloat16 g_postDwTH[DOUT * DOUT], g_postDwTL[DOUT * DOUT];
__device__ __nv_bfloat16 g_postGwTH[DOUT * DOUT], g_postGwTL[DOUT * DOUT];

// ------------------------- helpers -----------------------------------------
__device__ __forceinline__ uint32_t smem_u32(const void* p) {
    uint32_t a;
    asm("{ .reg .u64 t; cvta.to.shared.u64 t, %1; cvt.u32.u64 %0, t; }"
        : "=r"(a) : "l"(p));
    return a;
}
__device__ __forceinline__ void cp16(uint32_t s, const void* g) {
    asm volatile("cp.async.cg.shared.global [%0], [%1], 16;" :: "r"(s), "l"(g));
}
#define CP_COMMIT() asm volatile("cp.async.commit_group;")
#define CP_WAIT1()  asm volatile("cp.async.wait_group 1;")
#define CP_WAIT0()  asm volatile("cp.async.wait_group 0;")

__device__ __forceinline__ void ldmx4(uint32_t* r, uint32_t a) {
    asm volatile("ldmatrix.sync.aligned.m8n8.x4.shared.b16 {%0,%1,%2,%3}, [%4];"
        : "=r"(r[0]), "=r"(r[1]), "=r"(r[2]), "=r"(r[3]) : "r"(a));
}
__device__ __forceinline__ void mma_bf16(float* d, const uint32_t* a, const uint32_t* b) {
    asm volatile("mma.sync.aligned.m16n8k16.row.col.f32.bf16.bf16.f32 "
        "{%0,%1,%2,%3}, {%4,%5,%6,%7}, {%8,%9}, {%0,%1,%2,%3};"
        : "+f"(d[0]), "+f"(d[1]), "+f"(d[2]), "+f"(d[3])
        : "r"(a[0]), "r"(a[1]), "r"(a[2]), "r"(a[3]), "r"(b[0]), "r"(b[1]));
}
__device__ __forceinline__ float gelu_exact(float v) {
    return 0.5f * v * (1.0f + erff(v * 0.70710678118654752f));
}
__device__ __forceinline__ float sigmoidf_(float v) {
    return 1.0f / (1.0f + __expf(-v));
}
__device__ __forceinline__ void split_bf16(float v, __nv_bfloat16& h, __nv_bfloat16& l) {
    h = __float2bfloat16_rn(v);
    l = __float2bfloat16_rn(v - __bfloat162float(h));
}

// ------------------------- layernorm (emits bf16 hi/lo) ----------------------
template <int EPT, bool SPLIT_IN>
__global__ __launch_bounds__(256) void layernorm_split_kernel(
    const float* __restrict__ in, const float* __restrict__ gamma,
    const float* __restrict__ beta,
    __nv_bfloat16* __restrict__ oH, __nv_bfloat16* __restrict__ oL,
    __nv_bfloat16* __restrict__ iH, __nv_bfloat16* __restrict__ iL, int D)
{
    const int row = blockIdx.x;
    const int tid = threadIdx.x;
    const float* rp = in + (size_t)row * D;

    float v[EPT];
    float s = 0.f;
#pragma unroll
    for (int e = 0; e < EPT; e++) { v[e] = rp[tid + e * 256]; s += v[e]; }

    __shared__ float red[8];
    __shared__ float sMean, sVar;
#pragma unroll
    for (int o = 16; o > 0; o >>= 1) s += __shfl_down_sync(0xffffffffu, s, o);
    if ((tid & 31) == 0) red[tid >> 5] = s;
    __syncthreads();
    if (tid < 8) {
        float w = red[tid];
#pragma unroll
        for (int o = 4; o > 0; o >>= 1) w += __shfl_down_sync(0xffu, w, o);
        if (tid == 0) sMean = w / (float)D;
    }
    __syncthreads();
    const float mean = sMean;

    float q = 0.f;
#pragma unroll
    for (int e = 0; e < EPT; e++) { float d = v[e] - mean; q += d * d; }
#pragma unroll
    for (int o = 16; o > 0; o >>= 1) q += __shfl_down_sync(0xffffffffu, q, o);
    if ((tid & 31) == 0) red[tid >> 5] = q;
    __syncthreads();
    if (tid < 8) {
        float w = red[tid];
#pragma unroll
        for (int o = 4; o > 0; o >>= 1) w += __shfl_down_sync(0xffu, w, o);
        if (tid == 0) sVar = w / (float)D;
    }
    __syncthreads();
    const float inv = rsqrtf(sVar + 1e-6f);

    const size_t rb = (size_t)row * D;
#pragma unroll
    for (int e = 0; e < EPT; e++) {
        int c = tid + e * 256;
        float o = (v[e] - mean) * inv * gamma[c] + beta[c];
        __nv_bfloat16 h, l;
        split_bf16(o, h, l);
        oH[rb + c] = h; oL[rb + c] = l;
        if (SPLIT_IN) {
            split_bf16(v[e], h, l);
            iH[rb + c] = h; iL[rb + c] = l;
        }
    }
}

// ------------------------- TT operator materialization ----------------------
__global__ __launch_bounds__(256) void build_a01_kernel(
    const float* __restrict__ c0, const float* __restrict__ c1,
    float* __restrict__ a01)
{
    int idx = blockIdx.x * 256 + threadIdx.x;   // 131072
    int s = idx & 15, y = (idx >> 4) & 15, b = (idx >> 8) & 7;
    int x = (idx >> 11) & 7, a = idx >> 14;
    float acc = 0.f;
#pragma unroll
    for (int r = 0; r < 16; r++)
        acc += c0[a * 128 + x * 16 + r] * c1[((r * 8 + b) * 16 + y) * 16 + s];
    a01[idx] = acc;
}

__global__ __launch_bounds__(256) void build_wttT_kernel(
    const float* __restrict__ a01, const float* __restrict__ c2,
    __nv_bfloat16* __restrict__ wH, __nv_bfloat16* __restrict__ wL)
{
    int idx = blockIdx.x * 256 + threadIdx.x;   // 4096*1024
    int in  = idx & 1023;
    int out = idx >> 10;
    int z = out & 31, y = (out >> 5) & 15, x = out >> 9;
    int c = in & 15,  b = (in >> 4) & 7,   a = in >> 7;
    const float* ap = a01 + (((a * 8 + x) * 8 + b) * 16 + y) * 16;
    float acc = 0.f;
#pragma unroll
    for (int s = 0; s < 16; s++)
        acc += ap[s] * c2[(s * 16 + c) * 32 + z];
    __nv_bfloat16 h, l;
    split_bf16(acc, h, l);
    wH[idx] = h; wL[idx] = l;
}

// ------------------------- weight transpose + split --------------------------
__global__ __launch_bounds__(256) void transpose_split_kernel(
    const float* __restrict__ in, __nv_bfloat16* __restrict__ oH,
    __nv_bfloat16* __restrict__ oL, int K, int N)
{
    __shared__ float tile[32][33];
    int n0 = blockIdx.x * 32, k0 = blockIdx.y * 32;
    int tx = threadIdx.x & 31, ty = threadIdx.x >> 5;
#pragma unroll
    for (int i = 0; i < 4; i++)
        tile[ty + i * 8][tx] = in[(size_t)(k0 + ty + i * 8) * N + n0 + tx];
    __syncthreads();
#pragma unroll
    for (int i = 0; i < 4; i++) {
        float v = tile[tx][ty + i * 8];
        __nv_bfloat16 h, l;
        split_bf16(v, h, l);
        size_t o = (size_t)(n0 + ty + i * 8) * K + k0 + tx;
        oH[o] = h; oL[o] = l;
    }
}

// ------------------------- streaming combine: out = g*h + (1-g)*r -----------
__global__ __launch_bounds__(256) void combine_kernel(
    const float* __restrict__ g, const float* __restrict__ h,
    const float* __restrict__ r, float* __restrict__ out, int n4)
{
    int i = blockIdx.x * 256 + threadIdx.x;
    if (i < n4) {
        float4 gv = ((const float4*)g)[i];
        float4 hv = ((const float4*)h)[i];
        float4 rv = ((const float4*)r)[i];
        float4 o;
        o.x = gv.x * hv.x + (1.f - gv.x) * rv.x;
        o.y = gv.y * hv.y + (1.f - gv.y) * rv.y;
        o.z = gv.z * hv.z + (1.f - gv.z) * rv.z;
        o.w = gv.w * hv.w + (1.f - gv.w) * rv.w;
        ((float4*)out)[i] = o;
    }
}

// ------------------------- core mainloop (shared) ----------------------------
__device__ __forceinline__ void load_stage4(
    uint32_t sbase,
    const __nv_bfloat16* __restrict__ Ah, const __nv_bfloat16* __restrict__ Al,
    const __nv_bfloat16* __restrict__ Bh, const __nv_bfloat16* __restrict__ Bl,
    int aRow0, int bRow0, int K, int k0, int tid)
{
#pragma unroll
    for (int i = 0; i < 4; i++) {
        int idx = tid + i * NTHR;
        int r = idx >> 2, c = idx & 3;
        uint32_t so = swz(r, c);
        size_t ga = (size_t)(aRow0 + r) * K + k0 + c * 8;
        size_t gb = (size_t)(bRow0 + r) * K + k0 + c * 8;
        cp16(sbase + OFF_AH + so, Ah + ga);
        cp16(sbase + OFF_AL + so, Al + ga);
        cp16(sbase + OFF_BH + so, Bh + gb);
        cp16(sbase + OFF_BL + so, Bl + gb);
    }
}

// mainloop producing acc[4][8][4] for one 128x128 tile; warp tile 64x64
__device__ __forceinline__ void gemm_mainloop(
    uint32_t sm, float acc[4][8][4],
    const __nv_bfloat16* __restrict__ Ah, const __nv_bfloat16* __restrict__ Al,
    const __nv_bfloat16* __restrict__ Bh, const __nv_bfloat16* __restrict__ Bl,
    int blockM, int blockN, int K, int tid, int lane, int wm, int wn)
{
    const int nk = K / BK;
#pragma unroll
    for (int s = 0; s < STAGES - 1; s++) {
        load_stage4(sm + s * STAGE_BYTES, Ah, Al, Bh, Bl, blockM, blockN, K, s * BK, tid);
        CP_COMMIT();
    }
    const int aRow = lane & 15;
    const int aHi  = lane >> 4;
    const int bRow = wn + (lane & 7) + ((lane >> 4) << 3);
    const int bHi  = (lane >> 3) & 1;
    const int sA = ((aRow >> 1) & 3);
    const int sB = ((bRow >> 1) & 3);   // invariant under +16 row steps

    for (int t = 0; t < nk; t++) {
        CP_WAIT1();
        __syncthreads();
        const int pf = t + STAGES - 1;
        if (pf < nk)
            load_stage4(sm + (pf % STAGES) * STAGE_BYTES, Ah, Al, Bh, Bl,
                        blockM, blockN, K, pf * BK, tid);
        CP_COMMIT();

        const uint32_t sb = sm + (t % STAGES) * STAGE_BYTES;
#pragma unroll
        for (int ks = 0; ks < 2; ks++) {
            const uint32_t aChunk = (uint32_t)(((ks * 2 + aHi) ^ sA) << 4);
            const uint32_t bChunk = (uint32_t)(((ks * 2 + bHi) ^ sB) << 4);
            uint32_t ah[4][4], al[4][4];
#pragma unroll
            for (int mt = 0; mt < 4; mt++) {
                const uint32_t ra = (uint32_t)((wm + mt * 16 + aRow) * 64) + aChunk;
                ldmx4(ah[mt], sb + OFF_AH + ra);
                ldmx4(al[mt], sb + OFF_AL + ra);
            }
#pragma unroll
            for (int g = 0; g < 4; g++) {
                const uint32_t rg = (uint32_t)((bRow + g * 16) * 64) + bChunk;
                uint32_t bh0[4], bl0[4];
                ldmx4(bh0, sb + OFF_BH + rg);
                ldmx4(bl0, sb + OFF_BL + rg);
                // product-major: each run of 4 MMAs hits distinct accumulators
#pragma unroll
                for (int mt = 0; mt < 4; mt++) mma_bf16(acc[mt][2 * g + 0], ah[mt], bh0 + 0);
#pragma unroll
                for (int mt = 0; mt < 4; mt++) mma_bf16(acc[mt][2 * g + 1], ah[mt], bh0 + 2);
#pragma unroll
                for (int mt = 0; mt < 4; mt++) mma_bf16(acc[mt][2 * g + 0], ah[mt], bl0 + 0);
#pragma unroll
                for (int mt = 0; mt < 4; mt++) mma_bf16(acc[mt][2 * g + 1], ah[mt], bl0 + 2);
#pragma unroll
                for (int mt = 0; mt < 4; mt++) mma_bf16(acc[mt][2 * g + 0], al[mt], bh0 + 0);
#pragma unroll
                for (int mt = 0; mt < 4; mt++) mma_bf16(acc[mt][2 * g + 1], al[mt], bh0 + 2);
            }
        }
    }
    CP_WAIT0();
}

// ------------------------- GEMM kernels --------------------------------------
template <int OP>
__device__ __forceinline__ float epi_op(float acc, float b, float h, float r) {
    if (OP == OP_GELU) return gelu_exact(acc + b);
    if (OP == OP_GATE) { float g = sigmoidf_(acc + b); return g * h + (1.f - g) * r; }
    return acc;
}

template <int OP, bool WF32, bool WSPLIT>
__global__ __launch_bounds__(NTHR, 2) void mma_gemm_kernel(
    const __nv_bfloat16* __restrict__ Ah, const __nv_bfloat16* __restrict__ Al,
    const __nv_bfloat16* __restrict__ Bh, const __nv_bfloat16* __restrict__ Bl,
    const float* __restrict__ bias, const float* __restrict__ Hm,
    const float* __restrict__ Rm,
    float* __restrict__ CF, __nv_bfloat16* __restrict__ CH,
    __nv_bfloat16* __restrict__ CL, int M, int N, int K)
{
    extern __shared__ char smem[];
    const uint32_t sm = smem_u32(smem);
    const int tid  = threadIdx.x;
    const int lane = tid & 31;
    const int wid  = tid >> 5;
    const int blockM = blockIdx.x * BM;
    const int blockN = blockIdx.y * BN;
    const int wm = (wid >> 1) * 64;
    const int wn = (wid & 1) * 64;

    float acc[4][8][4];
#pragma unroll
    for (int i = 0; i < 4; i++)
#pragma unroll
        for (int j = 0; j < 8; j++)
#pragma unroll
            for (int e = 0; e < 4; e++) acc[i][j][e] = 0.f;

    gemm_mainloop(sm, acc, Ah, Al, Bh, Bl, blockM, blockN, K, tid, lane, wm, wn);

    const int r0 = lane >> 2;
    const int c0 = (lane & 3) * 2;
#pragma unroll
    for (int mt = 0; mt < 4; mt++) {
#pragma unroll
        for (int half = 0; half < 2; half++) {
            const int m = blockM + wm + mt * 16 + r0 + half * 8;
            const size_t base = (size_t)m * N;
#pragma unroll
            for (int nt = 0; nt < 8; nt++) {
                const int n = blockN + wn + nt * 8 + c0;
                float v0 = acc[mt][nt][half * 2 + 0];
                float v1 = acc[mt][nt][half * 2 + 1];
                float b0 = 0.f, b1 = 0.f, h0 = 0.f, h1 = 0.f, rr0 = 0.f, rr1 = 0.f;
                if (OP != OP_NONE) { b0 = bias[n]; b1 = bias[n + 1]; }
                if (OP == OP_GATE) {
                    float2 hh = *(const float2*)(Hm + base + n);
                    float2 rr = *(const float2*)(Rm + base + n);
                    h0 = hh.x; h1 = hh.y; rr0 = rr.x; rr1 = rr.y;
                }
                v0 = epi_op<OP>(v0, b0, h0, rr0);
                v1 = epi_op<OP>(v1, b1, h1, rr1);
                if (WF32) *(float2*)(CF + base + n) = make_float2(v0, v1);
                if (WSPLIT) {
                    __nv_bfloat16 hA, lA, hB, lB;
                    split_bf16(v0, hA, lA);
                    split_bf16(v1, hB, lB);
                    __nv_bfloat162 ph; ph.x = hA; ph.y = hB;
                    __nv_bfloat162 pl; pl.x = lA; pl.y = lB;
                    *(__nv_bfloat162*)(CH + base + n) = ph;
                    *(__nv_bfloat162*)(CL + base + n) = pl;
                }
            }
        }
    }
}

// merged post GEMM: z=0 dense->h2=gelu(acc+db), z=1 gate->g=sigmoid(acc+gb)
__global__ __launch_bounds__(NTHR, 2) void post_merged_kernel(
    const __nv_bfloat16* __restrict__ AdH, const __nv_bfloat16* __restrict__ AdL,
    const __nv_bfloat16* __restrict__ BdH, const __nv_bfloat16* __restrict__ BdL,
    const __nv_bfloat16* __restrict__ AgH, const __nv_bfloat16* __restrict__ AgL,
    const __nv_bfloat16* __restrict__ BgH, const __nv_bfloat16* __restrict__ BgL,
    const float* __restrict__ db, const float* __restrict__ gbv,
    float* __restrict__ h2, float* __restrict__ gbuf, int M, int N, int K)
{
    extern __shared__ char smem[];
    const uint32_t sm = smem_u32(smem);
    const int tid  = threadIdx.x;
    const int lane = tid & 31;
    const int wid  = tid >> 5;
    const int blockM = blockIdx.x * BM;
    const int blockN = blockIdx.y * BN;
    const int z = blockIdx.z;
    const int wm = (wid >> 1) * 64;
    const int wn = (wid & 1) * 64;

    const __nv_bfloat16* Ah = z ? AgH : AdH;
    const __nv_bfloat16* Al = z ? AgL : AdL;
    const __nv_bfloat16* Bh = z ? BgH : BdH;
    const __nv_bfloat16* Bl = z ? BgL : BdL;
    const float* bias = z ? gbv : db;
    float* CF = z ? gbuf : h2;

    float acc[4][8][4];
#pragma unroll
    for (int i = 0; i < 4; i++)
#pragma unroll
        for (int j = 0; j < 8; j++)
#pragma unroll
            for (int e = 0; e < 4; e++) acc[i][j][e] = 0.f;

    gemm_mainloop(sm, acc, Ah, Al, Bh, Bl, blockM, blockN, K, tid, lane, wm, wn);

    const int r0 = lane >> 2;
    const int c0 = (lane & 3) * 2;
#pragma unroll
    for (int mt = 0; mt < 4; mt++) {
#pragma unroll
        for (int half = 0; half < 2; half++) {
            const int m = blockM + wm + mt * 16 + r0 + half * 8;
            const size_t base = (size_t)m * N;
#pragma unroll
            for (int nt = 0; nt < 8; nt++) {
                const int n = blockN + wn + nt * 8 + c0;
                float v0 = acc[mt][nt][half * 2 + 0] + bias[n];
                float v1 = acc[mt][nt][half * 2 + 1] + bias[n + 1];
                if (z == 0) { v0 = gelu_exact(v0); v1 = gelu_exact(v1); }
                else        { v0 = sigmoidf_(v0);  v1 = sigmoidf_(v1);  }
                *(float2*)(CF + base + n) = make_float2(v0, v1);
            }
        }
    }
}

// ------------------------- launch ------------------------------------------
extern "C" void kernel_launch(void* const* d_in, const int* in_sizes, int n_in,
                              void* d_out, int out_size)
{
    const float* x      = (const float*)d_in[0];
    const float* preG   = (const float*)d_in[1];
    const float* preB   = (const float*)d_in[2];
    const float* preDw  = (const float*)d_in[3];
    const float* preDb  = (const float*)d_in[4];
    const float* preGw  = (const float*)d_in[5];
    const float* preGb  = (const float*)d_in[6];
    const float* core0  = (const float*)d_in[7];
    const float* core1  = (const float*)d_in[8];
    const float* core2  = (const float*)d_in[9];
    const float* postG  = (const float*)d_in[10];
    const float* postB  = (const float*)d_in[11];
    const float* postDw = (const float*)d_in[12];
    const float* postDb = (const float*)d_in[13];
    const float* postGw = (const float*)d_in[14];
    const float* postGb = (const float*)d_in[15];
    float* out = (float*)d_out;

    float *h1, *t, *h2, *gbuf, *a01;
    cudaGetSymbolAddress((void**)&h1,   g_h1);
    cudaGetSymbolAddress((void**)&t,    g_t);
    cudaGetSymbolAddress((void**)&h2,   g_h2);
    cudaGetSymbolAddress((void**)&gbuf, g_gb);
    cudaGetSymbolAddress((void**)&a01,  g_a01);

    __nv_bfloat16 *xH, *xL, *ln1H, *ln1L, *hpreH, *hpreL, *tH, *tL, *ln2H, *ln2L;
    __nv_bfloat16 *preDwTH, *preDwTL, *preGwTH, *preGwTL;
    __nv_bfloat16 *wttTH, *wttTL, *postDwTH, *postDwTL, *postGwTH, *postGwTL;
    cudaGetSymbolAddress((void**)&xH,    g_xH);    cudaGetSymbolAddress((void**)&xL,    g_xL);
    cudaGetSymbolAddress((void**)&ln1H,  g_ln1H);  cudaGetSymbolAddress((void**)&ln1L,  g_ln1L);
    cudaGetSymbolAddress((void**)&hpreH, g_hpreH); cudaGetSymbolAddress((void**)&hpreL, g_hpreL);
    cudaGetSymbolAddress((void**)&tH,    g_tH);    cudaGetSymbolAddress((void**)&tL,    g_tL);
    cudaGetSymbolAddress((void**)&ln2H,  g_ln2H);  cudaGetSymbolAddress((void**)&ln2L,  g_ln2L);
    cudaGetSymbolAddress((void**)&preDwTH,  g_preDwTH);  cudaGetSymbolAddress((void**)&preDwTL,  g_preDwTL);
    cudaGetSymbolAddress((void**)&preGwTH,  g_preGwTH);  cudaGetSymbolAddress((void**)&preGwTL,  g_preGwTL);
    cudaGetSymbolAddress((void**)&wttTH,    g_wttTH);    cudaGetSymbolAddress((void**)&wttTL,    g_wttTL);
    cudaGetSymbolAddress((void**)&postDwTH, g_postDwTH); cudaGetSymbolAddress((void**)&postDwTL, g_postDwTL);
    cudaGetSymbolAddress((void**)&postGwTH, g_postGwTH); cudaGetSymbolAddress((void**)&postGwTL, g_postGwTL);

    cudaFuncSetAttribute(mma_gemm_kernel<OP_GELU, true, false>,
                         cudaFuncAttributeMaxDynamicSharedMemorySize, GEMM_SMEM);
    cudaFuncSetAttribute(mma_gemm_kernel<OP_GATE, false, true>,
                         cudaFuncAttributeMaxDynamicSharedMemorySize, GEMM_SMEM);
    cudaFuncSetAttribute(mma_gemm_kernel<OP_NONE, true, true>,
                         cudaFuncAttributeMaxDynamicSharedMemorySize, GEMM_SMEM);
    cudaFuncSetAttribute(post_merged_kernel,
                         cudaFuncAttributeMaxDynamicSharedMemorySize, GEMM_SMEM);

    // --- operator prep (independent of x) ---
    build_a01_kernel<<<131072 / 256, 256>>>(core0, core1, a01);
    build_wttT_kernel<<<(DIN * DOUT) / 256, 256>>>(a01, core2, wttTH, wttTL);
    transpose_split_kernel<<<dim3(DIN / 32, DIN / 32), 256>>>(preDw, preDwTH, preDwTL, DIN, DIN);
    transpose_split_kernel<<<dim3(DIN / 32, DIN / 32), 256>>>(preGw, preGwTH, preGwTL, DIN, DIN);
    transpose_split_kernel<<<dim3(DOUT / 32, DOUT / 32), 256>>>(postDw, postDwTH, postDwTL, DOUT, DOUT);
    transpose_split_kernel<<<dim3(DOUT / 32, DOUT / 32), 256>>>(postGw, postGwTH, postGwTL, DOUT, DOUT);

    // --- pre block ---
    layernorm_split_kernel<DIN / 256, true><<<NTOK, 256>>>(
        x, preG, preB, ln1H, ln1L, xH, xL, DIN);
    mma_gemm_kernel<OP_GELU, true, false><<<dim3(NTOK / BM, DIN / BN), NTHR, GEMM_SMEM>>>(
        ln1H, ln1L, preDwTH, preDwTL, preDb, nullptr, nullptr,
        h1, nullptr, nullptr, NTOK, DIN, DIN);
    mma_gemm_kernel<OP_GATE, false, true><<<dim3(NTOK / BM, DIN / BN), NTHR, GEMM_SMEM>>>(
        xH, xL, preGwTH, preGwTL, preGb, h1, x,
        nullptr, hpreH, hpreL, NTOK, DIN, DIN);

    // --- TT contraction ---
    mma_gemm_kernel<OP_NONE, true, true><<<dim3(NTOK / BM, DOUT / BN), NTHR, GEMM_SMEM>>>(
        hpreH, hpreL, wttTH, wttTL, nullptr, nullptr, nullptr,
        t, tH, tL, NTOK, DOUT, DIN);

    // --- post block: LN, merged dense+gate (z), streaming combine ---
    layernorm_split_kernel<DOUT / 256, false><<<NTOK, 256>>>(
        t, postG, postB, ln2H, ln2L, nullptr, nullptr, DOUT);
    post_merged_kernel<<<dim3(NTOK / BM, DOUT / BN, 2), NTHR, GEMM_SMEM>>>(
        ln2H, ln2L, postDwTH, postDwTL,
        tH, tL, postGwTH, postGwTL,
        postDb, postGb, h2, gbuf, NTOK, DOUT, DOUT);
    combine_kernel<<<(NTOK * DOUT / 4 + 255) / 256, 256>>>(
        gbuf, h2, t, out, NTOK * DOUT / 4);
}

// round 14
// speedup vs baseline: 1.6760x; 1.0009x over previous
#include <cuda_runtime.h>
#include <cuda_bf16.h>
#include <math.h>
#include <stdint.h>

// ---------------------------------------------------------------------------
// HybridTTLayer via mma.sync bf16 tensor cores (plain sm_100 target).
// fp32 emulated as bf16 hi+lo split, 3-product MMA.
// R14 = R13 (best: 2486us) + software-pipelined B fragments (double-buffered
// across the g-loop) + cp.async issue moved after A-fragment loads + batched
// weight transposes. CTA 128x128, 4 warps, warp tile 64x64, 2 CTAs/SM.
// ---------------------------------------------------------------------------

#define NTOK   4096
#define DIN    1024
#define DOUT   4096

#define OP_NONE 0
#define OP_GELU 1
#define OP_GATE 2

// GEMM tiling
#define BM 128
#define BN 128
#define BK 32
#define NTHR 128
#define STAGES 3
#define OFF_AH 0
#define OFF_AL 8192
#define OFF_BH 16384
#define OFF_BL 24576
#define STAGE_BYTES 32768
#define GEMM_SMEM (STAGES * STAGE_BYTES)   // 98304 -> 2 CTAs/SM

// swizzled byte offset of 16B chunk c (0..3) in row r (64B rows)
__device__ __forceinline__ uint32_t swz(int r, int c) {
    return (uint32_t)(r * 64 + ((c ^ ((r >> 1) & 3)) << 4));
}

// ------------------------- scratch (static device memory) ------------------
__device__ float g_h1 [NTOK * DIN];
__device__ float g_t  [NTOK * DOUT];
__device__ float g_h2 [NTOK * DOUT];
__device__ float g_gb [NTOK * DOUT];      // post gate sigmoid buffer
__device__ float g_a01[8 * 8 * 8 * 16 * 16];
__device__ __nv_bfloat16 g_xH   [NTOK * DIN],  g_xL   [NTOK * DIN];
__device__ __nv_bfloat16 g_ln1H [NTOK * DIN],  g_ln1L [NTOK * DIN];
__device__ __nv_bfloat16 g_hpreH[NTOK * DIN],  g_hpreL[NTOK * DIN];
__device__ __nv_bfloat16 g_tH   [NTOK * DOUT], g_tL   [NTOK * DOUT];
__device__ __nv_bfloat16 g_ln2H [NTOK * DOUT], g_ln2L [NTOK * DOUT];
__device__ __nv_bfloat16 g_preDwTH [DIN * DIN],   g_preDwTL [DIN * DIN];
__device__ __nv_bfloat16 g_preGwTH [DIN * DIN],   g_preGwTL [DIN * DIN];
__device__ __nv_bfloat16 g_wttTH   [DOUT * DIN],  g_wttTL   [DOUT * DIN];
__device__ __nv_bfloat16 g_postDwTH[DOUT * DOUT], g_postDwTL[DOUT * DOUT];
__device__ __nv_bfloat16 g_postGwTH[DOUT * DOUT], g_postGwTL[DOUT * DOUT];

// ------------------------- helpers -----------------------------------------
__device__ __forceinline__ uint32_t smem_u32(const void* p) {
    uint32_t a;
    asm("{ .reg .u64 t; cvta.to.shared.u64 t, %1; cvt.u32.u64 %0, t; }"
        : "=r"(a) : "l"(p));
    return a;
}
__device__ __forceinline__ void cp16(uint32_t s, const void* g) {
    asm volatile("cp.async.cg.shared.global [%0], [%1], 16;" :: "r"(s), "l"(g));
}
#define CP_COMMIT() asm volatile("cp.async.commit_group;")
#define CP_WAIT1()  asm volatile("cp.async.wait_group 1;")
#define CP_WAIT0()  asm volatile("cp.async.wait_group 0;")

__device__ __forceinline__ void ldmx4(uint32_t* r, uint32_t a) {
    asm volatile("ldmatrix.sync.aligned.m8n8.x4.shared.b16 {%0,%1,%2,%3}, [%4];"
        : "=r"(r[0]), "=r"(r[1]), "=r"(r[2]), "=r"(r[3]) : "r"(a));
}
__device__ __forceinline__ void mma_bf16(float* d, const uint32_t* a, const uint32_t* b) {
    asm volatile("mma.sync.aligned.m16n8k16.row.col.f32.bf16.bf16.f32 "
        "{%0,%1,%2,%3}, {%4,%5,%6,%7}, {%8,%9}, {%0,%1,%2,%3};"
        : "+f"(d[0]), "+f"(d[1]), "+f"(d[2]), "+f"(d[3])
        : "r"(a[0]), "r"(a[1]), "r"(a[2]), "r"(a[3]), "r"(b[0]), "r"(b[1]));
}
__device__ __forceinline__ float gelu_exact(float v) {
    return 0.5f * v * (1.0f + erff(v * 0.70710678118654752f));
}
__device__ __forceinline__ float sigmoidf_(float v) {
    return 1.0f / (1.0f + __expf(-v));
}
__device__ __forceinline__ void split_bf16(float v, __nv_bfloat16& h, __nv_bfloat16& l) {
    h = __float2bfloat16_rn(v);
    l = __float2bfloat16_rn(v - __bfloat162float(h));
}

// ------------------------- layernorm (emits bf16 hi/lo) ----------------------
template <int EPT, bool SPLIT_IN>
__global__ __launch_bounds__(256) void layernorm_split_kernel(
    const float* __restrict__ in, const float* __restrict__ gamma,
    const float* __restrict__ beta,
    __nv_bfloat16* __restrict__ oH, __nv_bfloat16* __restrict__ oL,
    __nv_bfloat16* __restrict__ iH, __nv_bfloat16* __restrict__ iL, int D)
{
    const int row = blockIdx.x;
    const int tid = threadIdx.x;
    const float* rp = in + (size_t)row * D;

    float v[EPT];
    float s = 0.f;
#pragma unroll
    for (int e = 0; e < EPT; e++) { v[e] = rp[tid + e * 256]; s += v[e]; }

    __shared__ float red[8];
    __shared__ float sMean, sVar;
#pragma unroll
    for (int o = 16; o > 0; o >>= 1) s += __shfl_down_sync(0xffffffffu, s, o);
    if ((tid & 31) == 0) red[tid >> 5] = s;
    __syncthreads();
    if (tid < 8) {
        float w = red[tid];
#pragma unroll
        for (int o = 4; o > 0; o >>= 1) w += __shfl_down_sync(0xffu, w, o);
        if (tid == 0) sMean = w / (float)D;
    }
    __syncthreads();
    const float mean = sMean;

    float q = 0.f;
#pragma unroll
    for (int e = 0; e < EPT; e++) { float d = v[e] - mean; q += d * d; }
#pragma unroll
    for (int o = 16; o > 0; o >>= 1) q += __shfl_down_sync(0xffffffffu, q, o);
    if ((tid & 31) == 0) red[tid >> 5] = q;
    __syncthreads();
    if (tid < 8) {
        float w = red[tid];
#pragma unroll
        for (int o = 4; o > 0; o >>= 1) w += __shfl_down_sync(0xffu, w, o);
        if (tid == 0) sVar = w / (float)D;
    }
    __syncthreads();
    const float inv = rsqrtf(sVar + 1e-6f);

    const size_t rb = (size_t)row * D;
#pragma unroll
    for (int e = 0; e < EPT; e++) {
        int c = tid + e * 256;
        float o = (v[e] - mean) * inv * gamma[c] + beta[c];
        __nv_bfloat16 h, l;
        split_bf16(o, h, l);
        oH[rb + c] = h; oL[rb + c] = l;
        if (SPLIT_IN) {
            split_bf16(v[e], h, l);
            iH[rb + c] = h; iL[rb + c] = l;
        }
    }
}

// ------------------------- TT operator materialization ----------------------
__global__ __launch_bounds__(256) void build_a01_kernel(
    const float* __restrict__ c0, const float* __restrict__ c1,
    float* __restrict__ a01)
{
    int idx = blockIdx.x * 256 + threadIdx.x;   // 131072
    int s = idx & 15, y = (idx >> 4) & 15, b = (idx >> 8) & 7;
    int x = (idx >> 11) & 7, a = idx >> 14;
    float acc = 0.f;
#pragma unroll
    for (int r = 0; r < 16; r++)
        acc += c0[a * 128 + x * 16 + r] * c1[((r * 8 + b) * 16 + y) * 16 + s];
    a01[idx] = acc;
}

__global__ __launch_bounds__(256) void build_wttT_kernel(
    const float* __restrict__ a01, const float* __restrict__ c2,
    __nv_bfloat16* __restrict__ wH, __nv_bfloat16* __restrict__ wL)
{
    int idx = blockIdx.x * 256 + threadIdx.x;   // 4096*1024
    int in  = idx & 1023;
    int out = idx >> 10;
    int z = out & 31, y = (out >> 5) & 15, x = out >> 9;
    int c = in & 15,  b = (in >> 4) & 7,   a = in >> 7;
    const float* ap = a01 + (((a * 8 + x) * 8 + b) * 16 + y) * 16;
    float acc = 0.f;
#pragma unroll
    for (int s = 0; s < 16; s++)
        acc += ap[s] * c2[(s * 16 + c) * 32 + z];
    __nv_bfloat16 h, l;
    split_bf16(acc, h, l);
    wH[idx] = h; wL[idx] = l;
}

// ------------------------- batched weight transpose + split ------------------
// blockIdx.z selects which of two same-size weight matrices to transpose.
__global__ __launch_bounds__(256) void transpose_split2_kernel(
    const float* __restrict__ in0, __nv_bfloat16* __restrict__ o0H,
    __nv_bfloat16* __restrict__ o0L,
    const float* __restrict__ in1, __nv_bfloat16* __restrict__ o1H,
    __nv_bfloat16* __restrict__ o1L, int K, int N)
{
    const float* in = blockIdx.z ? in1 : in0;
    __nv_bfloat16* oH = blockIdx.z ? o1H : o0H;
    __nv_bfloat16* oL = blockIdx.z ? o1L : o0L;
    __shared__ float tile[32][33];
    int n0 = blockIdx.x * 32, k0 = blockIdx.y * 32;
    int tx = threadIdx.x & 31, ty = threadIdx.x >> 5;
#pragma unroll
    for (int i = 0; i < 4; i++)
        tile[ty + i * 8][tx] = in[(size_t)(k0 + ty + i * 8) * N + n0 + tx];
    __syncthreads();
#pragma unroll
    for (int i = 0; i < 4; i++) {
        float v = tile[tx][ty + i * 8];
        __nv_bfloat16 h, l;
        split_bf16(v, h, l);
        size_t o = (size_t)(n0 + ty + i * 8) * K + k0 + tx;
        oH[o] = h; oL[o] = l;
    }
}

// ------------------------- streaming combine: out = g*h + (1-g)*r -----------
__global__ __launch_bounds__(256) void combine_kernel(
    const float* __restrict__ g, const float* __restrict__ h,
    const float* __restrict__ r, float* __restrict__ out, int n4)
{
    int i = blockIdx.x * 256 + threadIdx.x;
    if (i < n4) {
        float4 gv = ((const float4*)g)[i];
        float4 hv = ((const float4*)h)[i];
        float4 rv = ((const float4*)r)[i];
        float4 o;
        o.x = gv.x * hv.x + (1.f - gv.x) * rv.x;
        o.y = gv.y * hv.y + (1.f - gv.y) * rv.y;
        o.z = gv.z * hv.z + (1.f - gv.z) * rv.z;
        o.w = gv.w * hv.w + (1.f - gv.w) * rv.w;
        ((float4*)out)[i] = o;
    }
}

// ------------------------- core mainloop (shared) ----------------------------
__device__ __forceinline__ void load_stage4(
    uint32_t sbase,
    const __nv_bfloat16* __restrict__ Ah, const __nv_bfloat16* __restrict__ Al,
    const __nv_bfloat16* __restrict__ Bh, const __nv_bfloat16* __restrict__ Bl,
    int aRow0, int bRow0, int K, int k0, int tid)
{
#pragma unroll
    for (int i = 0; i < 4; i++) {
        int idx = tid + i * NTHR;
        int r = idx >> 2, c = idx & 3;
        uint32_t so = swz(r, c);
        size_t ga = (size_t)(aRow0 + r) * K + k0 + c * 8;
        size_t gb = (size_t)(bRow0 + r) * K + k0 + c * 8;
        cp16(sbase + OFF_AH + so, Ah + ga);
        cp16(sbase + OFF_AL + so, Al + ga);
        cp16(sbase + OFF_BH + so, Bh + gb);
        cp16(sbase + OFF_BL + so, Bl + gb);
    }
}

// mainloop producing acc[4][8][4] for one 128x128 tile; warp tile 64x64.
// B fragments double-buffered across the g-loop so the tensor pipe always has
// a full MMA batch queued while the next LDSM streams.
__device__ __forceinline__ void gemm_mainloop(
    uint32_t sm, float acc[4][8][4],
    const __nv_bfloat16* __restrict__ Ah, const __nv_bfloat16* __restrict__ Al,
    const __nv_bfloat16* __restrict__ Bh, const __nv_bfloat16* __restrict__ Bl,
    int blockM, int blockN, int K, int tid, int lane, int wm, int wn)
{
    const int nk = K / BK;
#pragma unroll
    for (int s = 0; s < STAGES - 1; s++) {
        load_stage4(sm + s * STAGE_BYTES, Ah, Al, Bh, Bl, blockM, blockN, K, s * BK, tid);
        CP_COMMIT();
    }
    const int aRow = lane & 15;
    const int aHi  = lane >> 4;
    const int bRow = wn + (lane & 7) + ((lane >> 4) << 3);
    const int bHi  = (lane >> 3) & 1;
    const int sA = ((aRow >> 1) & 3);
    const int sB = ((bRow >> 1) & 3);   // invariant under +16 row steps

    for (int t = 0; t < nk; t++) {
        CP_WAIT1();
        __syncthreads();
        const int pf = t + STAGES - 1;
        const uint32_t sb = sm + (t % STAGES) * STAGE_BYTES;

#pragma unroll
        for (int ks = 0; ks < 2; ks++) {
            const uint32_t aChunk = (uint32_t)(((ks * 2 + aHi) ^ sA) << 4);
            const uint32_t bChunk = (uint32_t)(((ks * 2 + bHi) ^ sB) << 4);
            uint32_t ah[4][4], al[4][4];
#pragma unroll
            for (int mt = 0; mt < 4; mt++) {
                const uint32_t ra = (uint32_t)((wm + mt * 16 + aRow) * 64) + aChunk;
                ldmx4(ah[mt], sb + OFF_AH + ra);
                ldmx4(al[mt], sb + OFF_AL + ra);
            }
            // issue next-stage cp.async between A-frag loads and the MMA body
            // (only once per chunk, on ks==0)
            if (ks == 0) {
                if (pf < nk)
                    load_stage4(sm + (pf % STAGES) * STAGE_BYTES, Ah, Al, Bh, Bl,
                                blockM, blockN, K, pf * BK, tid);
                CP_COMMIT();
            }
            // B double buffer: preload g=0
            uint32_t bh[2][4], bl[2][4];
            {
                const uint32_t rg = (uint32_t)(bRow * 64) + bChunk;
                ldmx4(bh[0], sb + OFF_BH + rg);
                ldmx4(bl[0], sb + OFF_BL + rg);
            }
#pragma unroll
            for (int g = 0; g < 4; g++) {
                const int cur = g & 1;
                const int nxt = cur ^ 1;
                if (g < 3) {
                    const uint32_t rg = (uint32_t)((bRow + (g + 1) * 16) * 64) + bChunk;
                    ldmx4(bh[nxt], sb + OFF_BH + rg);
                    ldmx4(bl[nxt], sb + OFF_BL + rg);
                }
                // product-major: each run of 4 MMAs hits distinct accumulators
#pragma unroll
                for (int mt = 0; mt < 4; mt++) mma_bf16(acc[mt][2 * g + 0], ah[mt], bh[cur] + 0);
#pragma unroll
                for (int mt = 0; mt < 4; mt++) mma_bf16(acc[mt][2 * g + 1], ah[mt], bh[cur] + 2);
#pragma unroll
                for (int mt = 0; mt < 4; mt++) mma_bf16(acc[mt][2 * g + 0], ah[mt], bl[cur] + 0);
#pragma unroll
                for (int mt = 0; mt < 4; mt++) mma_bf16(acc[mt][2 * g + 1], ah[mt], bl[cur] + 2);
#pragma unroll
                for (int mt = 0; mt < 4; mt++) mma_bf16(acc[mt][2 * g + 0], al[mt], bh[cur] + 0);
#pragma unroll
                for (int mt = 0; mt < 4; mt++) mma_bf16(acc[mt][2 * g + 1], al[mt], bh[cur] + 2);
            }
        }
    }
    CP_WAIT0();
}

// ------------------------- GEMM kernels --------------------------------------
template <int OP>
__device__ __forceinline__ float epi_op(float acc, float b, float h, float r) {
    if (OP == OP_GELU) return gelu_exact(acc + b);
    if (OP == OP_GATE) { float g = sigmoidf_(acc + b); return g * h + (1.f - g) * r; }
    return acc;
}

template <int OP, bool WF32, bool WSPLIT>
__global__ __launch_bounds__(NTHR, 2) void mma_gemm_kernel(
    const __nv_bfloat16* __restrict__ Ah, const __nv_bfloat16* __restrict__ Al,
    const __nv_bfloat16* __restrict__ Bh, const __nv_bfloat16* __restrict__ Bl,
    const float* __restrict__ bias, const float* __restrict__ Hm,
    const float* __restrict__ Rm,
    float* __restrict__ CF, __nv_bfloat16* __restrict__ CH,
    __nv_bfloat16* __restrict__ CL, int M, int N, int K)
{
    extern __shared__ char smem[];
    const uint32_t sm = smem_u32(smem);
    const int tid  = threadIdx.x;
    const int lane = tid & 31;
    const int wid  = tid >> 5;
    const int blockM = blockIdx.x * BM;
    const int blockN = blockIdx.y * BN;
    const int wm = (wid >> 1) * 64;
    const int wn = (wid & 1) * 64;

    float acc[4][8][4];
#pragma unroll
    for (int i = 0; i < 4; i++)
#pragma unroll
        for (int j = 0; j < 8; j++)
#pragma unroll
            for (int e = 0; e < 4; e++) acc[i][j][e] = 0.f;

    gemm_mainloop(sm, acc, Ah, Al, Bh, Bl, blockM, blockN, K, tid, lane, wm, wn);

    const int r0 = lane >> 2;
    const int c0 = (lane & 3) * 2;
#pragma unroll
    for (int mt = 0; mt < 4; mt++) {
#pragma unroll
        for (int half = 0; half < 2; half++) {
            const int m = blockM + wm + mt * 16 + r0 + half * 8;
            const size_t base = (size_t)m * N;
#pragma unroll
            for (int nt = 0; nt < 8; nt++) {
                const int n = blockN + wn + nt * 8 + c0;
                float v0 = acc[mt][nt][half * 2 + 0];
                float v1 = acc[mt][nt][half * 2 + 1];
                float b0 = 0.f, b1 = 0.f, h0 = 0.f, h1 = 0.f, rr0 = 0.f, rr1 = 0.f;
                if (OP != OP_NONE) { b0 = bias[n]; b1 = bias[n + 1]; }
                if (OP == OP_GATE) {
                    float2 hh = *(const float2*)(Hm + base + n);
                    float2 rr = *(const float2*)(Rm + base + n);
                    h0 = hh.x; h1 = hh.y; rr0 = rr.x; rr1 = rr.y;
                }
                v0 = epi_op<OP>(v0, b0, h0, rr0);
                v1 = epi_op<OP>(v1, b1, h1, rr1);
                if (WF32) *(float2*)(CF + base + n) = make_float2(v0, v1);
                if (WSPLIT) {
                    __nv_bfloat16 hA, lA, hB, lB;
                    split_bf16(v0, hA, lA);
                    split_bf16(v1, hB, lB);
                    __nv_bfloat162 ph; ph.x = hA; ph.y = hB;
                    __nv_bfloat162 pl; pl.x = lA; pl.y = lB;
                    *(__nv_bfloat162*)(CH + base + n) = ph;
                    *(__nv_bfloat162*)(CL + base + n) = pl;
                }
            }
        }
    }
}

// merged post GEMM: z=0 dense->h2=gelu(acc+db), z=1 gate->g=sigmoid(acc+gb)
__global__ __launch_bounds__(NTHR, 2) void post_merged_kernel(
    const __nv_bfloat16* __restrict__ AdH, const __nv_bfloat16* __restrict__ AdL,
    const __nv_bfloat16* __restrict__ BdH, const __nv_bfloat16* __restrict__ BdL,
    const __nv_bfloat16* __restrict__ AgH, const __nv_bfloat16* __restrict__ AgL,
    const __nv_bfloat16* __restrict__ BgH, const __nv_bfloat16* __restrict__ BgL,
    const float* __restrict__ db, const float* __restrict__ gbv,
    float* __restrict__ h2, float* __restrict__ gbuf, int M, int N, int K)
{
    extern __shared__ char smem[];
    const uint32_t sm = smem_u32(smem);
    const int tid  = threadIdx.x;
    const int lane = tid & 31;
    const int wid  = tid >> 5;
    const int blockM = blockIdx.x * BM;
    const int blockN = blockIdx.y * BN;
    const int z = blockIdx.z;
    const int wm = (wid >> 1) * 64;
    const int wn = (wid & 1) * 64;

    const __nv_bfloat16* Ah = z ? AgH : AdH;
    const __nv_bfloat16* Al = z ? AgL : AdL;
    const __nv_bfloat16* Bh = z ? BgH : BdH;
    const __nv_bfloat16* Bl = z ? BgL : BdL;
    const float* bias = z ? gbv : db;
    float* CF = z ? gbuf : h2;

    float acc[4][8][4];
#pragma unroll
    for (int i = 0; i < 4; i++)
#pragma unroll
        for (int j = 0; j < 8; j++)
#pragma unroll
            for (int e = 0; e < 4; e++) acc[i][j][e] = 0.f;

    gemm_mainloop(sm, acc, Ah, Al, Bh, Bl, blockM, blockN, K, tid, lane, wm, wn);

    const int r0 = lane >> 2;
    const int c0 = (lane & 3) * 2;
#pragma unroll
    for (int mt = 0; mt < 4; mt++) {
#pragma unroll
        for (int half = 0; half < 2; half++) {
            const int m = blockM + wm + mt * 16 + r0 + half * 8;
            const size_t base = (size_t)m * N;
#pragma unroll
            for (int nt = 0; nt < 8; nt++) {
                const int n = blockN + wn + nt * 8 + c0;
                float v0 = acc[mt][nt][half * 2 + 0] + bias[n];
                float v1 = acc[mt][nt][half * 2 + 1] + bias[n + 1];
                if (z == 0) { v0 = gelu_exact(v0); v1 = gelu_exact(v1); }
                else        { v0 = sigmoidf_(v0);  v1 = sigmoidf_(v1);  }
                *(float2*)(CF + base + n) = make_float2(v0, v1);
            }
        }
    }
}

// ------------------------- launch ------------------------------------------
extern "C" void kernel_launch(void* const* d_in, const int* in_sizes, int n_in,
                              void* d_out, int out_size)
{
    const float* x      = (const float*)d_in[0];
    const float* preG   = (const float*)d_in[1];
    const float* preB   = (const float*)d_in[2];
    const float* preDw  = (const float*)d_in[3];
    const float* preDb  = (const float*)d_in[4];
    const float* preGw  = (const float*)d_in[5];
    const float* preGb  = (const float*)d_in[6];
    const float* core0  = (const float*)d_in[7];
    const float* core1  = (const float*)d_in[8];
    const float* core2  = (const float*)d_in[9];
    const float* postG  = (const float*)d_in[10];
    const float* postB  = (const float*)d_in[11];
    const float* postDw = (const float*)d_in[12];
    const float* postDb = (const float*)d_in[13];
    const float* postGw = (const float*)d_in[14];
    const float* postGb = (const float*)d_in[15];
    float* out = (float*)d_out;

    float *h1, *t, *h2, *gbuf, *a01;
    cudaGetSymbolAddress((void**)&h1,   g_h1);
    cudaGetSymbolAddress((void**)&t,    g_t);
    cudaGetSymbolAddress((void**)&h2,   g_h2);
    cudaGetSymbolAddress((void**)&gbuf, g_gb);
    cudaGetSymbolAddress((void**)&a01,  g_a01);

    __nv_bfloat16 *xH, *xL, *ln1H, *ln1L, *hpreH, *hpreL, *tH, *tL, *ln2H, *ln2L;
    __nv_bfloat16 *preDwTH, *preDwTL, *preGwTH, *preGwTL;
    __nv_bfloat16 *wttTH, *wttTL, *postDwTH, *postDwTL, *postGwTH, *postGwTL;
    cudaGetSymbolAddress((void**)&xH,    g_xH);    cudaGetSymbolAddress((void**)&xL,    g_xL);
    cudaGetSymbolAddress((void**)&ln1H,  g_ln1H);  cudaGetSymbolAddress((void**)&ln1L,  g_ln1L);
    cudaGetSymbolAddress((void**)&hpreH, g_hpreH); cudaGetSymbolAddress((void**)&hpreL, g_hpreL);
    cudaGetSymbolAddress((void**)&tH,    g_tH);    cudaGetSymbolAddress((void**)&tL,    g_tL);
    cudaGetSymbolAddress((void**)&ln2H,  g_ln2H);  cudaGetSymbolAddress((void**)&ln2L,  g_ln2L);
    cudaGetSymbolAddress((void**)&preDwTH,  g_preDwTH);  cudaGetSymbolAddress((void**)&preDwTL,  g_preDwTL);
    cudaGetSymbolAddress((void**)&preGwTH,  g_preGwTH);  cudaGetSymbolAddress((void**)&preGwTL,  g_preGwTL);
    cudaGetSymbolAddress((void**)&wttTH,    g_wttTH);    cudaGetSymbolAddress((void**)&wttTL,    g_wttTL);
    cudaGetSymbolAddress((void**)&postDwTH, g_postDwTH); cudaGetSymbolAddress((void**)&postDwTL, g_postDwTL);
    cudaGetSymbolAddress((void**)&postGwTH, g_postGwTH); cudaGetSymbolAddress((void**)&postGwTL, g_postGwTL);

    cudaFuncSetAttribute(mma_gemm_kernel<OP_GELU, true, false>,
                         cudaFuncAttributeMaxDynamicSharedMemorySize, GEMM_SMEM);
    cudaFuncSetAttribute(mma_gemm_kernel<OP_GATE, false, true>,
                         cudaFuncAttributeMaxDynamicSharedMemorySize, GEMM_SMEM);
    cudaFuncSetAttribute(mma_gemm_kernel<OP_NONE, true, true>,
                         cudaFuncAttributeMaxDynamicSharedMemorySize, GEMM_SMEM);
    cudaFuncSetAttribute(post_merged_kernel,
                         cudaFuncAttributeMaxDynamicSharedMemorySize, GEMM_SMEM);

    // --- operator prep (independent of x) ---
    build_a01_kernel<<<131072 / 256, 256>>>(core0, core1, a01);
    build_wttT_kernel<<<(DIN * DOUT) / 256, 256>>>(a01, core2, wttTH, wttTL);
    transpose_split2_kernel<<<dim3(DIN / 32, DIN / 32, 2), 256>>>(
        preDw, preDwTH, preDwTL, preGw, preGwTH, preGwTL, DIN, DIN);
    transpose_split2_kernel<<<dim3(DOUT / 32, DOUT / 32, 2), 256>>>(
        postDw, postDwTH, postDwTL, postGw, postGwTH, postGwTL, DOUT, DOUT);

    // --- pre block ---
    layernorm_split_kernel<DIN / 256, true><<<NTOK, 256>>>(
        x, preG, preB, ln1H, ln1L, xH, xL, DIN);
    mma_gemm_kernel<OP_GELU, true, false><<<dim3(NTOK / BM, DIN / BN), NTHR, GEMM_SMEM>>>(
        ln1H, ln1L, preDwTH, preDwTL, preDb, nullptr, nullptr,
        h1, nullptr, nullptr, NTOK, DIN, DIN);
    mma_gemm_kernel<OP_GATE, false, true><<<dim3(NTOK / BM, DIN / BN), NTHR, GEMM_SMEM>>>(
        xH, xL, preGwTH, preGwTL, preGb, h1, x,
        nullptr, hpreH, hpreL, NTOK, DIN, DIN);

    // --- TT contraction ---
    mma_gemm_kernel<OP_NONE, true, true><<<dim3(NTOK / BM, DOUT / BN), NTHR, GEMM_SMEM>>>(
        hpreH, hpreL, wttTH, wttTL, nullptr, nullptr, nullptr,
        t, tH, tL, NTOK, DOUT, DIN);

    // --- post block: LN, merged dense+gate (z), streaming combine ---
    layernorm_split_kernel<DOUT / 256, false><<<NTOK, 256>>>(
        t, postG, postB, ln2H, ln2L, nullptr, nullptr, DOUT);
    post_merged_kernel<<<dim3(NTOK / BM, DOUT / BN, 2), NTHR, GEMM_SMEM>>>(
        ln2H, ln2L, postDwTH, postDwTL,
        tH, tL, postGwTH, postGwTL,
        postDb, postGb, h2, gbuf, NTOK, DOUT, DOUT);
    combine_kernel<<<(NTOK * DOUT / 4 + 255) / 256, 256>>>(
        gbuf, h2, t, out, NTOK * DOUT / 4);
}